// round 7
// baseline (speedup 1.0000x reference)
#include <cuda_runtime.h>
#include <cuda_bf16.h>
#include <math.h>
#include <stdint.h>

// ---------------- problem constants ----------------
#define BNUM 32
#define HH   56
#define WW   56
#define CC   192
#define NHH  6
#define HD   32
#define WSZ  7
#define SSZ  3
#define NN   49
#define NWIN 64
#define TOK  (BNUM*HH*WW)   // 100352
#define HIDD 768

typedef __nv_bfloat16 bf16;

// ---------------- scratch ----------------
__device__ bf16  g_xw  [(size_t)TOK*CC];      // LN1 out (bf16, windowed)
__device__ bf16  g_qkv [(size_t)TOK*3*CC];    // qkv (bf16)
__device__ bf16  g_attn[(size_t)TOK*CC];      // attention out (bf16, windowed)
__device__ float g_y   [(size_t)TOK*CC];      // x + attn branch (fp32, natural)
__device__ bf16  g_xm  [(size_t)TOK*CC];      // LN2 out (bf16)
__device__ bf16  g_h   [(size_t)TOK*HIDD];    // fc1+GELU out (bf16)
__device__ float g_tab [4*6*49*64];           // bias+mask tables
// transposed bf16 weights [N][K]
__device__ bf16  g_wqkv[(size_t)576*192];
__device__ bf16  g_wprj[(size_t)192*192];
__device__ bf16  g_wfc1[(size_t)HIDD*192];
__device__ bf16  g_wfc2[(size_t)192*HIDD];

// ---------------- PTX helpers ----------------
__device__ __forceinline__ uint32_t smem_u32(const void* p) {
    uint32_t a;
    asm("{ .reg .u64 t; cvta.to.shared.u64 t, %1; cvt.u32.u64 %0, t; }"
        : "=r"(a) : "l"(p));
    return a;
}
__device__ __forceinline__ void cp16(uint32_t s, const void* g) {
    asm volatile("cp.async.cg.shared.global [%0], [%1], 16;" :: "r"(s), "l"(g));
}
#define CP_COMMIT() asm volatile("cp.async.commit_group;" ::: "memory")
__device__ __forceinline__ void ldsm4(uint32_t& r0, uint32_t& r1, uint32_t& r2,
                                      uint32_t& r3, uint32_t a) {
    asm volatile("ldmatrix.sync.aligned.m8n8.x4.shared.b16 {%0,%1,%2,%3}, [%4];"
                 : "=r"(r0), "=r"(r1), "=r"(r2), "=r"(r3) : "r"(a));
}
__device__ __forceinline__ void ldsm4t(uint32_t& r0, uint32_t& r1, uint32_t& r2,
                                       uint32_t& r3, uint32_t a) {
    asm volatile("ldmatrix.sync.aligned.m8n8.x4.trans.shared.b16 {%0,%1,%2,%3}, [%4];"
                 : "=r"(r0), "=r"(r1), "=r"(r2), "=r"(r3) : "r"(a));
}
__device__ __forceinline__ void mma_bf16(float* c, const uint32_t* a, const uint32_t* b) {
    asm volatile(
        "mma.sync.aligned.m16n8k16.row.col.f32.bf16.bf16.f32 "
        "{%0,%1,%2,%3}, {%4,%5,%6,%7}, {%8,%9}, {%0,%1,%2,%3};"
        : "+f"(c[0]), "+f"(c[1]), "+f"(c[2]), "+f"(c[3])
        : "r"(a[0]), "r"(a[1]), "r"(a[2]), "r"(a[3]), "r"(b[0]), "r"(b[1]));
}
__device__ __forceinline__ uint32_t packbf2(float lo, float hi) {
    __nv_bfloat162 h2 = __floats2bfloat162_rn(lo, hi);
    return *reinterpret_cast<uint32_t*>(&h2);
}

// ---------------- weight transpose + bf16 convert: W[K,N] -> Wt[N,K] ------
__global__ void wtrans_kernel(const float* __restrict__ W, bf16* __restrict__ Wt,
                              int K, int N)
{
    __shared__ float tile[32][33];
    int k0 = blockIdx.y * 32, n0 = blockIdx.x * 32;
    int tx = threadIdx.x, ty = threadIdx.y;   // 32 x 8
#pragma unroll
    for (int i = 0; i < 32; i += 8)
        tile[ty + i][tx] = W[(size_t)(k0 + ty + i) * N + n0 + tx];
    __syncthreads();
#pragma unroll
    for (int i = 0; i < 32; i += 8)
        Wt[(size_t)(n0 + ty + i) * K + k0 + tx] = __float2bfloat16(tile[tx][ty + i]);
}

// ---------------- bias+mask table precompute --------------------
__global__ void tab_kernel(const float* __restrict__ rel_bias)
{
    int bh = blockIdx.x;              // 0..23 = mi*6 + h
    int mi = bh / 6, h = bh % 6;
    int eh = mi >> 1, ew = mi & 1;
    for (int idx = threadIdx.x; idx < NN * 64; idx += 256) {
        int i = idx >> 6, j = idx & 63;
        float val;
        if (j >= NN) val = -1e30f;
        else {
            int ih = i / WSZ, iw = i % WSZ, jh = j / WSZ, jw = j % WSZ;
            int dh = ih - jh + (WSZ - 1), dw = iw - jw + (WSZ - 1);
            float bias = rel_bias[(dh * (2 * WSZ - 1) + dw) * NHH + h];
            int ai = eh ? (ih < WSZ - SSZ ? 1 : 2) : 0;
            int bi = ew ? (iw < WSZ - SSZ ? 1 : 2) : 0;
            int aj = eh ? (jh < WSZ - SSZ ? 1 : 2) : 0;
            int bj = ew ? (jw < WSZ - SSZ ? 1 : 2) : 0;
            float mask = ((ai * 3 + bi) != (aj * 3 + bj)) ? -100.0f : 0.0f;
            val = bias + mask;
        }
        g_tab[(size_t)bh * (NN * 64) + idx] = val;
    }
}

// ---------------- LayerNorm (warp per token), bf16 output -----------------
template<int MODE>
__global__ void ln_kernel(const float* __restrict__ x,
                          const float* __restrict__ gamma,
                          const float* __restrict__ beta)
{
    int warp = (blockIdx.x * blockDim.x + threadIdx.x) >> 5;
    int lane = threadIdx.x & 31;
    if (warp >= TOK) return;

    const float* src;
    bf16* dst;
    if (MODE == 0) {
        int tw = warp;
        int w  = tw / NN, n = tw % NN;
        int bb = w / NWIN, wi = w % NWIN;
        int wrow = wi >> 3, wcol = wi & 7;
        int ih = n / WSZ, iw = n % WSZ;
        int gh = wrow * WSZ + ih + SSZ; if (gh >= HH) gh -= HH;
        int gw = wcol * WSZ + iw + SSZ; if (gw >= WW) gw -= WW;
        src = x + ((size_t)bb * HH * WW + (size_t)gh * WW + gw) * CC;
        dst = g_xw + (size_t)tw * CC;
    } else {
        src = g_y + (size_t)warp * CC;
        dst = g_xm + (size_t)warp * CC;
    }

    float v[6];
    float s = 0.f;
#pragma unroll
    for (int k = 0; k < 6; k++) { v[k] = src[lane + 32 * k]; s += v[k]; }
#pragma unroll
    for (int o = 16; o; o >>= 1) s += __shfl_xor_sync(0xffffffffu, s, o);
    float mean = s * (1.0f / CC);
    float vs = 0.f;
#pragma unroll
    for (int k = 0; k < 6; k++) { float d = v[k] - mean; vs += d * d; }
#pragma unroll
    for (int o = 16; o; o >>= 1) vs += __shfl_xor_sync(0xffffffffu, vs, o);
    float inv = rsqrtf(vs * (1.0f / CC) + 1e-5f);
#pragma unroll
    for (int k = 0; k < 6; k++) {
        int c = lane + 32 * k;
        dst[c] = __float2bfloat16((v[k] - mean) * inv * gamma[c] + beta[c]);
    }
}

// ================= bf16 mma GEMM =================
// BM=128, BN=96, BK=32. 256 threads = 8 warps (4m x 2n), warp tile 32x48.
// RESM: 0 none, 1 residual (natural), 2 scatter window-reverse + residual.
#define SROW 40              // bf16 per smem row (80 B)
#define A_BUF_B (128 * SROW * 2)
#define B_BUF_B (96  * SROW * 2)

template<int ACT, int RESM, bool OBF>
__global__ void __launch_bounds__(256)
gemm_bf16(const bf16* __restrict__ A, const bf16* __restrict__ Wt,
          const float* __restrict__ bias, const float* __restrict__ res,
          void* __restrict__ Cv, int M, int N, int K)
{
    __shared__ __align__(16) bf16 As[2][128 * SROW];
    __shared__ __align__(16) bf16 Bs[2][96 * SROW];

    const int t    = threadIdx.x;
    const int lane = t & 31;
    const int wid  = t >> 5;
    const int wm   = wid & 3;
    const int wn   = wid >> 2;
    const int m0   = blockIdx.y << 7;
    const int n0   = blockIdx.x * 96;

    const uint32_t asB = smem_u32(As);
    const uint32_t bsB = smem_u32(Bs);

    const int T = K >> 5;
    const int a_row = t >> 2, a_kc = (t & 3) << 3;   // A: 2 chunks/thread

    auto load_tiles = [&](int kt, int b) {
        const int k0 = kt << 5;
        uint32_t aD = asB + b * A_BUF_B;
        cp16(aD + a_row * 80 + (a_kc << 1),
             A + (size_t)(m0 + a_row) * K + k0 + a_kc);
        cp16(aD + (a_row + 64) * 80 + (a_kc << 1),
             A + (size_t)(m0 + a_row + 64) * K + k0 + a_kc);
        // B: 96 rows x 4 chunks = 384 chunks
        uint32_t bD = bsB + b * B_BUF_B;
        {
            int i = t;
            cp16(bD + (i >> 2) * 80 + ((i & 3) << 4),
                 Wt + (size_t)(n0 + (i >> 2)) * K + k0 + ((i & 3) << 3));
        }
        if (t < 128) {
            int i = t + 256;
            cp16(bD + (i >> 2) * 80 + ((i & 3) << 4),
                 Wt + (size_t)(n0 + (i >> 2)) * K + k0 + ((i & 3) << 3));
        }
        CP_COMMIT();
    };

    float acc[2][6][4];
#pragma unroll
    for (int i = 0; i < 2; i++)
#pragma unroll
        for (int j = 0; j < 6; j++)
#pragma unroll
            for (int q = 0; q < 4; q++) acc[i][j][q] = 0.f;

    const uint32_t aFrag = (wm * 32 + (lane & 15)) * 80 + ((lane >> 4) << 4);
    const uint32_t bFrag = (wn * 48 + (lane & 7) + (((lane >> 4) & 1) << 3)) * 80
                           + (((lane >> 3) & 1) << 4);

    load_tiles(0, 0);

    for (int kt = 0; kt < T; kt++) {
        const int b = kt & 1;
        if (kt + 1 < T) {
            load_tiles(kt + 1, b ^ 1);
            asm volatile("cp.async.wait_group 1;" ::: "memory");
        } else {
            asm volatile("cp.async.wait_group 0;" ::: "memory");
        }
        __syncthreads();

        const uint32_t aB = asB + b * A_BUF_B + aFrag;
        const uint32_t bB = bsB + b * B_BUF_B + bFrag;
#pragma unroll
        for (int kk = 0; kk < 2; kk++) {
            uint32_t av[2][4], bv[6][2];
            ldsm4(av[0][0], av[0][1], av[0][2], av[0][3], aB + kk * 32);
            ldsm4(av[1][0], av[1][1], av[1][2], av[1][3], aB + 16 * 80 + kk * 32);
#pragma unroll
            for (int g = 0; g < 3; g++)
                ldsm4(bv[2 * g][0], bv[2 * g][1], bv[2 * g + 1][0], bv[2 * g + 1][1],
                      bB + g * 16 * 80 + kk * 32);
#pragma unroll
            for (int mt = 0; mt < 2; mt++)
#pragma unroll
                for (int nt = 0; nt < 6; nt++)
                    mma_bf16(acc[mt][nt], av[mt], bv[nt]);
        }
        __syncthreads();
    }

    // ---------------- epilogue ----------------
    const int colBase = n0 + wn * 48 + ((lane & 3) << 1);
    const int rowBase = m0 + wm * 32 + (lane >> 2);
#pragma unroll
    for (int mt = 0; mt < 2; mt++) {
#pragma unroll
        for (int half = 0; half < 2; half++) {
            const int r = rowBase + mt * 16 + half * 8;
            size_t outRow = (size_t)r;
            if (RESM == 2) {
                int wq = r / NN, nq = r % NN;
                int bq = wq >> 6, wiq = wq & 63;
                int gh = (wiq >> 3) * WSZ + nq / WSZ + SSZ; if (gh >= HH) gh -= HH;
                int gw = (wiq & 7)  * WSZ + nq % WSZ + SSZ; if (gw >= WW) gw -= WW;
                outRow = (size_t)bq * (HH * WW) + gh * WW + gw;
            }
            const float* Rrow = res + outRow * N;
#pragma unroll
            for (int nt = 0; nt < 6; nt++) {
                const int c0 = colBase + nt * 8;
                float v0 = acc[mt][nt][half * 2 + 0] + bias[c0];
                float v1 = acc[mt][nt][half * 2 + 1] + bias[c0 + 1];
                if (ACT == 1) {
                    v0 = 0.5f * v0 * (1.0f + erff(v0 * 0.70710678118654752f));
                    v1 = 0.5f * v1 * (1.0f + erff(v1 * 0.70710678118654752f));
                }
                if (RESM != 0) { v0 += Rrow[c0]; v1 += Rrow[c0 + 1]; }
                if (OBF) {
                    bf16* Crow = (bf16*)Cv + outRow * N;
                    *(__nv_bfloat162*)&Crow[c0] = __floats2bfloat162_rn(v0, v1);
                } else {
                    float* Crow = (float*)Cv + outRow * N;
                    float2 o; o.x = v0; o.y = v1;
                    *(float2*)&Crow[c0] = o;
                }
            }
        }
    }
}

// ================= tensor-core windowed attention =================
__global__ void __launch_bounds__(128)
attn_mma_kernel()
{
    __shared__ __align__(16) bf16 Qs[64 * SROW];
    __shared__ __align__(16) bf16 Ks[64 * SROW];
    __shared__ __align__(16) bf16 Vs[64 * SROW];

    const int blk = blockIdx.x;
    const int w = blk / NHH, h = blk % NHH;
    const int t = threadIdx.x;
    const int lane = t & 31, mt = t >> 5;

    const uint32_t qB = smem_u32(Qs), kB = smem_u32(Ks), vB = smem_u32(Vs);

    for (int i = t; i < 15 * 20; i += 128) {
        int off = (49 + i / 20) * 20 + (i % 20);
        ((uint32_t*)Qs)[off] = 0;
        ((uint32_t*)Ks)[off] = 0;
        ((uint32_t*)Vs)[off] = 0;
    }

    const bf16* base = g_qkv + (size_t)w * NN * (3 * CC) + h * HD;
    for (int i = t; i < NN * 4; i += 128) {
        int r = i >> 2, c = (i & 3) << 3;
        const bf16* src = base + (size_t)r * (3 * CC) + c;
        cp16(qB + r * 80 + (c << 1), src);
        cp16(kB + r * 80 + (c << 1), src + CC);
        cp16(vB + r * 80 + (c << 1), src + 2 * CC);
    }
    CP_COMMIT();
    asm volatile("cp.async.wait_group 0;" ::: "memory");
    __syncthreads();

    // ---- S = Q K^T ----
    float sacc[8][4];
#pragma unroll
    for (int i = 0; i < 8; i++)
#pragma unroll
        for (int q = 0; q < 4; q++) sacc[i][q] = 0.f;

    const uint32_t aAddr = qB + (mt * 16 + (lane & 15)) * 80 + ((lane >> 4) << 4);
    const uint32_t bAddr = kB + ((lane & 7) + (((lane >> 4) & 1) << 3)) * 80
                              + (((lane >> 3) & 1) << 4);
#pragma unroll
    for (int kk = 0; kk < 2; kk++) {
        uint32_t av[4];
        ldsm4(av[0], av[1], av[2], av[3], aAddr + kk * 32);
#pragma unroll
        for (int ng = 0; ng < 4; ng++) {
            uint32_t b0, b1, b2, b3;
            ldsm4(b0, b1, b2, b3, bAddr + ng * 16 * 80 + kk * 32);
            uint32_t bv0[2] = {b0, b1}, bv1[2] = {b2, b3};
            mma_bf16(sacc[2 * ng],     av, bv0);
            mma_bf16(sacc[2 * ng + 1], av, bv1);
        }
    }

    // ---- scale + table + softmax in fragments ----
    const int wi = w & (NWIN - 1);
    const int mi = (((wi >> 3) == 7) ? 2 : 0) + (((wi & 7) == 7) ? 1 : 0);
    const float* tb = g_tab + (size_t)(mi * NHH + h) * (NN * 64);
    const int r0 = mt * 16 + (lane >> 2);
    const float scale = 0.17677669529663687f;

#pragma unroll
    for (int nt = 0; nt < 8; nt++) {
        const int c = nt * 8 + ((lane & 3) << 1);
        float t00 = 0.f, t01 = 0.f, t10 = 0.f, t11 = 0.f;
        if (r0 < NN)     { float2 tt = *(const float2*)&tb[r0 * 64 + c];      t00 = tt.x; t01 = tt.y; }
        if (r0 + 8 < NN) { float2 tt = *(const float2*)&tb[(r0 + 8) * 64 + c]; t10 = tt.x; t11 = tt.y; }
        sacc[nt][0] = sacc[nt][0] * scale + t00;
        sacc[nt][1] = sacc[nt][1] * scale + t01;
        sacc[nt][2] = sacc[nt][2] * scale + t10;
        sacc[nt][3] = sacc[nt][3] * scale + t11;
    }

    float m0 = -1e30f, m1 = -1e30f;
#pragma unroll
    for (int nt = 0; nt < 8; nt++) {
        m0 = fmaxf(m0, fmaxf(sacc[nt][0], sacc[nt][1]));
        m1 = fmaxf(m1, fmaxf(sacc[nt][2], sacc[nt][3]));
    }
    m0 = fmaxf(m0, __shfl_xor_sync(0xffffffffu, m0, 1));
    m0 = fmaxf(m0, __shfl_xor_sync(0xffffffffu, m0, 2));
    m1 = fmaxf(m1, __shfl_xor_sync(0xffffffffu, m1, 1));
    m1 = fmaxf(m1, __shfl_xor_sync(0xffffffffu, m1, 2));

    float s0 = 0.f, s1 = 0.f;
#pragma unroll
    for (int nt = 0; nt < 8; nt++) {
        sacc[nt][0] = __expf(sacc[nt][0] - m0);
        sacc[nt][1] = __expf(sacc[nt][1] - m0);
        sacc[nt][2] = __expf(sacc[nt][2] - m1);
        sacc[nt][3] = __expf(sacc[nt][3] - m1);
        s0 += sacc[nt][0] + sacc[nt][1];
        s1 += sacc[nt][2] + sacc[nt][3];
    }
    s0 += __shfl_xor_sync(0xffffffffu, s0, 1);
    s0 += __shfl_xor_sync(0xffffffffu, s0, 2);
    s1 += __shfl_xor_sync(0xffffffffu, s1, 1);
    s1 += __shfl_xor_sync(0xffffffffu, s1, 2);
    const float i0 = 1.0f / s0, i1 = 1.0f / s1;

    // ---- O = P V ----
    float oacc[4][4];
#pragma unroll
    for (int i = 0; i < 4; i++)
#pragma unroll
        for (int q = 0; q < 4; q++) oacc[i][q] = 0.f;

    const uint32_t vAddr = vB + ((((lane >> 3) & 1) << 3) + (lane & 7)) * 80
                              + (((lane >> 4) & 1) << 4);
#pragma unroll
    for (int kk = 0; kk < 4; kk++) {
        uint32_t pa[4];
        pa[0] = packbf2(sacc[2 * kk][0] * i0,     sacc[2 * kk][1] * i0);
        pa[1] = packbf2(sacc[2 * kk][2] * i1,     sacc[2 * kk][3] * i1);
        pa[2] = packbf2(sacc[2 * kk + 1][0] * i0, sacc[2 * kk + 1][1] * i0);
        pa[3] = packbf2(sacc[2 * kk + 1][2] * i1, sacc[2 * kk + 1][3] * i1);
        uint32_t b0, b1, b2, b3;
        ldsm4t(b0, b1, b2, b3, vAddr + kk * 16 * 80);
        { uint32_t bv0[2] = {b0, b1}, bv1[2] = {b2, b3};
          mma_bf16(oacc[0], pa, bv0); mma_bf16(oacc[1], pa, bv1); }
        ldsm4t(b0, b1, b2, b3, vAddr + kk * 16 * 80 + 32);
        { uint32_t bv0[2] = {b0, b1}, bv1[2] = {b2, b3};
          mma_bf16(oacc[2], pa, bv0); mma_bf16(oacc[3], pa, bv1); }
    }

    bf16* outB = g_attn + (size_t)w * NN * CC + h * HD;
#pragma unroll
    for (int nt = 0; nt < 4; nt++) {
        const int c = nt * 8 + ((lane & 3) << 1);
        if (r0 < NN)
            *(__nv_bfloat162*)&outB[(size_t)r0 * CC + c] =
                __floats2bfloat162_rn(oacc[nt][0], oacc[nt][1]);
        if (r0 + 8 < NN)
            *(__nv_bfloat162*)&outB[(size_t)(r0 + 8) * CC + c] =
                __floats2bfloat162_rn(oacc[nt][2], oacc[nt][3]);
    }
}

// ---------------- launch ----------------
extern "C" void kernel_launch(void* const* d_in, const int* in_sizes, int n_in,
                              void* d_out, int out_size)
{
    const float* x       = (const float*)d_in[0];
    const float* norm1_g = (const float*)d_in[1];
    const float* norm1_b = (const float*)d_in[2];
    const float* qkv_w   = (const float*)d_in[3];
    const float* qkv_b   = (const float*)d_in[4];
    const float* rel_b   = (const float*)d_in[5];
    const float* proj_w  = (const float*)d_in[6];
    const float* proj_b  = (const float*)d_in[7];
    const float* norm2_g = (const float*)d_in[8];
    const float* norm2_b = (const float*)d_in[9];
    const float* fc1_w   = (const float*)d_in[10];
    const float* fc1_b   = (const float*)d_in[11];
    const float* fc2_w   = (const float*)d_in[12];
    const float* fc2_b   = (const float*)d_in[13];
    float* out = (float*)d_out;

    bf16 *p_xw, *p_qkv, *p_attn, *p_xm, *p_h, *p_wqkv, *p_wprj, *p_wfc1, *p_wfc2;
    float *p_y;
    cudaGetSymbolAddress((void**)&p_xw,   g_xw);
    cudaGetSymbolAddress((void**)&p_qkv,  g_qkv);
    cudaGetSymbolAddress((void**)&p_attn, g_attn);
    cudaGetSymbolAddress((void**)&p_y,    g_y);
    cudaGetSymbolAddress((void**)&p_xm,   g_xm);
    cudaGetSymbolAddress((void**)&p_h,    g_h);
    cudaGetSymbolAddress((void**)&p_wqkv, g_wqkv);
    cudaGetSymbolAddress((void**)&p_wprj, g_wprj);
    cudaGetSymbolAddress((void**)&p_wfc1, g_wfc1);
    cudaGetSymbolAddress((void**)&p_wfc2, g_wfc2);

    const int lnBlocks = TOK / 8;
    dim3 wtb(32, 8);

    // 0) weight transposes + bias/mask tables
    wtrans_kernel<<<dim3(576 / 32, 192 / 32), wtb>>>(qkv_w, p_wqkv, CC, 3 * CC);
    wtrans_kernel<<<dim3(192 / 32, 192 / 32), wtb>>>(proj_w, p_wprj, CC, CC);
    wtrans_kernel<<<dim3(HIDD / 32, 192 / 32), wtb>>>(fc1_w, p_wfc1, CC, HIDD);
    wtrans_kernel<<<dim3(192 / 32, HIDD / 32), wtb>>>(fc2_w, p_wfc2, HIDD, CC);
    tab_kernel<<<24, 256>>>(rel_b);

    // 1) LN1 + shift + window partition (bf16)
    ln_kernel<0><<<lnBlocks, 256>>>(x, norm1_g, norm1_b);

    // 2) QKV gemm [TOK,192]x[192,576] -> bf16
    gemm_bf16<0, 0, true><<<dim3(576 / 96, TOK / 128), 256>>>(
        p_xw, p_wqkv, qkv_b, nullptr, p_qkv, TOK, 3 * CC, CC);

    // 3) tensor-core windowed attention
    attn_mma_kernel<<<(TOK / NN) * NHH, 128>>>();

    // 4) proj gemm + window-reverse/unshift scatter + residual -> g_y (fp32)
    gemm_bf16<0, 2, false><<<dim3(192 / 96, TOK / 128), 256>>>(
        p_attn, p_wprj, proj_b, x, p_y, TOK, CC, CC);

    // 5) LN2 (bf16)
    ln_kernel<1><<<lnBlocks, 256>>>(nullptr, norm2_g, norm2_b);

    // 6) fc1 + exact GELU [TOK,192]x[192,768] -> bf16
    gemm_bf16<1, 0, true><<<dim3(HIDD / 96, TOK / 128), 256>>>(
        p_xm, p_wfc1, fc1_b, nullptr, p_h, TOK, HIDD, CC);

    // 7) fc2 + residual [TOK,768]x[768,192] -> d_out (fp32)
    gemm_bf16<0, 1, false><<<dim3(192 / 96, TOK / 128), 256>>>(
        p_h, p_wfc2, fc2_b, p_y, out, TOK, CC, HIDD);
}

// round 8
// speedup vs baseline: 1.0028x; 1.0028x over previous
#include <cuda_runtime.h>
#include <cuda_bf16.h>
#include <math.h>
#include <stdint.h>

// ---------------- problem constants ----------------
#define BNUM 32
#define HH   56
#define WW   56
#define CC   192
#define NHH  6
#define HD   32
#define WSZ  7
#define SSZ  3
#define NN   49
#define NWIN 64
#define TOK  (BNUM*HH*WW)   // 100352
#define HIDD 768

typedef __nv_bfloat16 bf16;

// ---------------- scratch ----------------
__device__ bf16  g_xw  [(size_t)TOK*CC];      // LN1 out (bf16, windowed)
__device__ bf16  g_qkv [(size_t)TOK*3*CC];    // qkv (bf16)
__device__ bf16  g_attn[(size_t)TOK*CC];      // attention out (bf16, windowed)
__device__ float g_y   [(size_t)TOK*CC];      // x + attn branch (fp32, natural)
__device__ bf16  g_xm  [(size_t)TOK*CC];      // LN2 out (bf16)
__device__ bf16  g_h   [(size_t)TOK*HIDD];    // fc1+GELU out (bf16)
__device__ float g_tab [4*6*49*64];           // bias+mask tables
// transposed bf16 weights [N][K]
__device__ bf16  g_wqkv[(size_t)576*192];
__device__ bf16  g_wprj[(size_t)192*192];
__device__ bf16  g_wfc1[(size_t)HIDD*192];
__device__ bf16  g_wfc2[(size_t)192*HIDD];

// ---------------- PTX helpers ----------------
__device__ __forceinline__ uint32_t smem_u32(const void* p) {
    uint32_t a;
    asm("{ .reg .u64 t; cvta.to.shared.u64 t, %1; cvt.u32.u64 %0, t; }"
        : "=r"(a) : "l"(p));
    return a;
}
__device__ __forceinline__ void cp16(uint32_t s, const void* g) {
    asm volatile("cp.async.cg.shared.global [%0], [%1], 16;" :: "r"(s), "l"(g));
}
#define CP_COMMIT() asm volatile("cp.async.commit_group;" ::: "memory")
__device__ __forceinline__ void ldsm4(uint32_t& r0, uint32_t& r1, uint32_t& r2,
                                      uint32_t& r3, uint32_t a) {
    asm volatile("ldmatrix.sync.aligned.m8n8.x4.shared.b16 {%0,%1,%2,%3}, [%4];"
                 : "=r"(r0), "=r"(r1), "=r"(r2), "=r"(r3) : "r"(a));
}
__device__ __forceinline__ void ldsm4t(uint32_t& r0, uint32_t& r1, uint32_t& r2,
                                       uint32_t& r3, uint32_t a) {
    asm volatile("ldmatrix.sync.aligned.m8n8.x4.trans.shared.b16 {%0,%1,%2,%3}, [%4];"
                 : "=r"(r0), "=r"(r1), "=r"(r2), "=r"(r3) : "r"(a));
}
__device__ __forceinline__ void mma_bf16(float* c, const uint32_t* a, const uint32_t* b) {
    asm volatile(
        "mma.sync.aligned.m16n8k16.row.col.f32.bf16.bf16.f32 "
        "{%0,%1,%2,%3}, {%4,%5,%6,%7}, {%8,%9}, {%0,%1,%2,%3};"
        : "+f"(c[0]), "+f"(c[1]), "+f"(c[2]), "+f"(c[3])
        : "r"(a[0]), "r"(a[1]), "r"(a[2]), "r"(a[3]), "r"(b[0]), "r"(b[1]));
}
__device__ __forceinline__ uint32_t packbf2(float lo, float hi) {
    __nv_bfloat162 h2 = __floats2bfloat162_rn(lo, hi);
    return *reinterpret_cast<uint32_t*>(&h2);
}

// ---------------- weight transpose + bf16 convert: W[K,N] -> Wt[N,K] ------
__global__ void wtrans_kernel(const float* __restrict__ W, bf16* __restrict__ Wt,
                              int K, int N)
{
    __shared__ float tile[32][33];
    int k0 = blockIdx.y * 32, n0 = blockIdx.x * 32;
    int tx = threadIdx.x, ty = threadIdx.y;   // 32 x 8
#pragma unroll
    for (int i = 0; i < 32; i += 8)
        tile[ty + i][tx] = W[(size_t)(k0 + ty + i) * N + n0 + tx];
    __syncthreads();
#pragma unroll
    for (int i = 0; i < 32; i += 8)
        Wt[(size_t)(n0 + ty + i) * K + k0 + tx] = __float2bfloat16(tile[tx][ty + i]);
}

// ---------------- bias+mask table precompute --------------------
__global__ void tab_kernel(const float* __restrict__ rel_bias)
{
    int bh = blockIdx.x;              // 0..23 = mi*6 + h
    int mi = bh / 6, h = bh % 6;
    int eh = mi >> 1, ew = mi & 1;
    for (int idx = threadIdx.x; idx < NN * 64; idx += 256) {
        int i = idx >> 6, j = idx & 63;
        float val;
        if (j >= NN) val = -1e30f;
        else {
            int ih = i / WSZ, iw = i % WSZ, jh = j / WSZ, jw = j % WSZ;
            int dh = ih - jh + (WSZ - 1), dw = iw - jw + (WSZ - 1);
            float bias = rel_bias[(dh * (2 * WSZ - 1) + dw) * NHH + h];
            int ai = eh ? (ih < WSZ - SSZ ? 1 : 2) : 0;
            int bi = ew ? (iw < WSZ - SSZ ? 1 : 2) : 0;
            int aj = eh ? (jh < WSZ - SSZ ? 1 : 2) : 0;
            int bj = ew ? (jw < WSZ - SSZ ? 1 : 2) : 0;
            float mask = ((ai * 3 + bi) != (aj * 3 + bj)) ? -100.0f : 0.0f;
            val = bias + mask;
        }
        g_tab[(size_t)bh * (NN * 64) + idx] = val;
    }
}

// ---------------- LayerNorm (warp per token), bf16 output -----------------
template<int MODE>
__global__ void ln_kernel(const float* __restrict__ x,
                          const float* __restrict__ gamma,
                          const float* __restrict__ beta)
{
    int warp = (blockIdx.x * blockDim.x + threadIdx.x) >> 5;
    int lane = threadIdx.x & 31;
    if (warp >= TOK) return;

    const float* src;
    bf16* dst;
    if (MODE == 0) {
        int tw = warp;
        int w  = tw / NN, n = tw % NN;
        int bb = w / NWIN, wi = w % NWIN;
        int wrow = wi >> 3, wcol = wi & 7;
        int ih = n / WSZ, iw = n % WSZ;
        int gh = wrow * WSZ + ih + SSZ; if (gh >= HH) gh -= HH;
        int gw = wcol * WSZ + iw + SSZ; if (gw >= WW) gw -= WW;
        src = x + ((size_t)bb * HH * WW + (size_t)gh * WW + gw) * CC;
        dst = g_xw + (size_t)tw * CC;
    } else {
        src = g_y + (size_t)warp * CC;
        dst = g_xm + (size_t)warp * CC;
    }

    float v[6];
    float s = 0.f;
#pragma unroll
    for (int k = 0; k < 6; k++) { v[k] = src[lane + 32 * k]; s += v[k]; }
#pragma unroll
    for (int o = 16; o; o >>= 1) s += __shfl_xor_sync(0xffffffffu, s, o);
    float mean = s * (1.0f / CC);
    float vs = 0.f;
#pragma unroll
    for (int k = 0; k < 6; k++) { float d = v[k] - mean; vs += d * d; }
#pragma unroll
    for (int o = 16; o; o >>= 1) vs += __shfl_xor_sync(0xffffffffu, vs, o);
    float inv = rsqrtf(vs * (1.0f / CC) + 1e-5f);
#pragma unroll
    for (int k = 0; k < 6; k++) {
        int c = lane + 32 * k;
        dst[c] = __float2bfloat16((v[k] - mean) * inv * gamma[c] + beta[c]);
    }
}

// ================= bf16 mma GEMM =================
// BM=128, BN=64, BK=32. 256 threads = 8 warps (4m x 2n), warp tile 32x32.
// 3-stage cp.async ring, ONE __syncthreads per K-tile.
// RESM: 0 none, 1 residual (natural), 2 scatter window-reverse + residual.
#define SROW 40              // bf16 per smem row (80 B)
#define A_STG (128 * SROW)   // elements per A stage
#define B_STG (64  * SROW)

template<int ACT, int RESM, bool OBF>
__global__ void __launch_bounds__(256)
gemm_bf16(const bf16* __restrict__ A, const bf16* __restrict__ Wt,
          const float* __restrict__ bias, const float* __restrict__ res,
          void* __restrict__ Cv, int M, int N, int K)
{
    __shared__ __align__(16) bf16 As[3][A_STG];
    __shared__ __align__(16) bf16 Bs[3][B_STG];

    const int t    = threadIdx.x;
    const int lane = t & 31;
    const int wid  = t >> 5;
    const int wm   = wid & 3;
    const int wn   = wid >> 2;
    const int m0   = blockIdx.y << 7;
    const int n0   = blockIdx.x << 6;

    const uint32_t asB = smem_u32(As);
    const uint32_t bsB = smem_u32(Bs);

    const int T = K >> 5;
    const int a_row = t >> 2, a_kc = (t & 3) << 3;

    auto load_tiles = [&](int kt, int s) {
        const int k0 = kt << 5;
        uint32_t aD = asB + s * (A_STG * 2);
        cp16(aD + a_row * 80 + (a_kc << 1),
             A + (size_t)(m0 + a_row) * K + k0 + a_kc);
        cp16(aD + (a_row + 64) * 80 + (a_kc << 1),
             A + (size_t)(m0 + a_row + 64) * K + k0 + a_kc);
        uint32_t bD = bsB + s * (B_STG * 2);
        cp16(bD + a_row * 80 + (a_kc << 1),
             Wt + (size_t)(n0 + a_row) * K + k0 + a_kc);
        CP_COMMIT();
    };

    float acc[2][4][4];
#pragma unroll
    for (int i = 0; i < 2; i++)
#pragma unroll
        for (int j = 0; j < 4; j++)
#pragma unroll
            for (int q = 0; q < 4; q++) acc[i][j][q] = 0.f;

    const uint32_t aFrag = (wm * 32 + (lane & 15)) * 80 + ((lane >> 4) << 4);
    const uint32_t bFrag = (wn * 32 + (lane & 7) + (((lane >> 4) & 1) << 3)) * 80
                           + (((lane >> 3) & 1) << 4);

    load_tiles(0, 0);
    load_tiles(1, 1);

    int s = 0, sNext = 2;            // stage of tile kt; stage to fill with kt+2
    for (int kt = 0; kt < T; kt++) {
        if (kt + 1 < T) {
            asm volatile("cp.async.wait_group 1;" ::: "memory");
        } else {
            asm volatile("cp.async.wait_group 0;" ::: "memory");
        }
        __syncthreads();
        if (kt + 2 < T) {
            load_tiles(kt + 2, sNext);
        }

        const uint32_t aB = asB + s * (A_STG * 2) + aFrag;
        const uint32_t bB = bsB + s * (B_STG * 2) + bFrag;
#pragma unroll
        for (int kk = 0; kk < 2; kk++) {
            uint32_t av[2][4], bv[4][2];
            ldsm4(av[0][0], av[0][1], av[0][2], av[0][3], aB + kk * 32);
            ldsm4(av[1][0], av[1][1], av[1][2], av[1][3], aB + 16 * 80 + kk * 32);
            ldsm4(bv[0][0], bv[0][1], bv[1][0], bv[1][1], bB + kk * 32);
            ldsm4(bv[2][0], bv[2][1], bv[3][0], bv[3][1], bB + 16 * 80 + kk * 32);
#pragma unroll
            for (int mt = 0; mt < 2; mt++)
#pragma unroll
                for (int nt = 0; nt < 4; nt++)
                    mma_bf16(acc[mt][nt], av[mt], bv[nt]);
        }
        s = (s == 2) ? 0 : s + 1;
        sNext = (sNext == 2) ? 0 : sNext + 1;
    }

    // ---------------- epilogue ----------------
    const int colBase = n0 + wn * 32 + ((lane & 3) << 1);
    const int rowBase = m0 + wm * 32 + (lane >> 2);
#pragma unroll
    for (int mt = 0; mt < 2; mt++) {
#pragma unroll
        for (int half = 0; half < 2; half++) {
            const int r = rowBase + mt * 16 + half * 8;
            size_t outRow = (size_t)r;
            if (RESM == 2) {
                int wq = r / NN, nq = r % NN;
                int bq = wq >> 6, wiq = wq & 63;
                int gh = (wiq >> 3) * WSZ + nq / WSZ + SSZ; if (gh >= HH) gh -= HH;
                int gw = (wiq & 7)  * WSZ + nq % WSZ + SSZ; if (gw >= WW) gw -= WW;
                outRow = (size_t)bq * (HH * WW) + gh * WW + gw;
            }
            const float* Rrow = res + outRow * N;
#pragma unroll
            for (int nt = 0; nt < 4; nt++) {
                const int c0 = colBase + nt * 8;
                float v0 = acc[mt][nt][half * 2 + 0] + bias[c0];
                float v1 = acc[mt][nt][half * 2 + 1] + bias[c0 + 1];
                if (ACT == 1) {
                    v0 = 0.5f * v0 * (1.0f + erff(v0 * 0.70710678118654752f));
                    v1 = 0.5f * v1 * (1.0f + erff(v1 * 0.70710678118654752f));
                }
                if (RESM != 0) { v0 += Rrow[c0]; v1 += Rrow[c0 + 1]; }
                if (OBF) {
                    bf16* Crow = (bf16*)Cv + outRow * N;
                    *(__nv_bfloat162*)&Crow[c0] = __floats2bfloat162_rn(v0, v1);
                } else {
                    float* Crow = (float*)Cv + outRow * N;
                    float2 o; o.x = v0; o.y = v1;
                    *(float2*)&Crow[c0] = o;
                }
            }
        }
    }
}

// ================= tensor-core windowed attention =================
__global__ void __launch_bounds__(128)
attn_mma_kernel()
{
    __shared__ __align__(16) bf16 Qs[64 * SROW];
    __shared__ __align__(16) bf16 Ks[64 * SROW];
    __shared__ __align__(16) bf16 Vs[64 * SROW];

    const int blk = blockIdx.x;
    const int w = blk / NHH, h = blk % NHH;
    const int t = threadIdx.x;
    const int lane = t & 31, mt = t >> 5;

    const uint32_t qB = smem_u32(Qs), kB = smem_u32(Ks), vB = smem_u32(Vs);

    for (int i = t; i < 15 * 20; i += 128) {
        int off = (49 + i / 20) * 20 + (i % 20);
        ((uint32_t*)Qs)[off] = 0;
        ((uint32_t*)Ks)[off] = 0;
        ((uint32_t*)Vs)[off] = 0;
    }

    const bf16* base = g_qkv + (size_t)w * NN * (3 * CC) + h * HD;
    for (int i = t; i < NN * 4; i += 128) {
        int r = i >> 2, c = (i & 3) << 3;
        const bf16* src = base + (size_t)r * (3 * CC) + c;
        cp16(qB + r * 80 + (c << 1), src);
        cp16(kB + r * 80 + (c << 1), src + CC);
        cp16(vB + r * 80 + (c << 1), src + 2 * CC);
    }
    CP_COMMIT();
    asm volatile("cp.async.wait_group 0;" ::: "memory");
    __syncthreads();

    // ---- S = Q K^T ----
    float sacc[8][4];
#pragma unroll
    for (int i = 0; i < 8; i++)
#pragma unroll
        for (int q = 0; q < 4; q++) sacc[i][q] = 0.f;

    const uint32_t aAddr = qB + (mt * 16 + (lane & 15)) * 80 + ((lane >> 4) << 4);
    const uint32_t bAddr = kB + ((lane & 7) + (((lane >> 4) & 1) << 3)) * 80
                              + (((lane >> 3) & 1) << 4);
#pragma unroll
    for (int kk = 0; kk < 2; kk++) {
        uint32_t av[4];
        ldsm4(av[0], av[1], av[2], av[3], aAddr + kk * 32);
#pragma unroll
        for (int ng = 0; ng < 4; ng++) {
            uint32_t b0, b1, b2, b3;
            ldsm4(b0, b1, b2, b3, bAddr + ng * 16 * 80 + kk * 32);
            uint32_t bv0[2] = {b0, b1}, bv1[2] = {b2, b3};
            mma_bf16(sacc[2 * ng],     av, bv0);
            mma_bf16(sacc[2 * ng + 1], av, bv1);
        }
    }

    // ---- scale + table + softmax in fragments ----
    const int wi = w & (NWIN - 1);
    const int mi = (((wi >> 3) == 7) ? 2 : 0) + (((wi & 7) == 7) ? 1 : 0);
    const float* tb = g_tab + (size_t)(mi * NHH + h) * (NN * 64);
    const int r0 = mt * 16 + (lane >> 2);
    const float scale = 0.17677669529663687f;

#pragma unroll
    for (int nt = 0; nt < 8; nt++) {
        const int c = nt * 8 + ((lane & 3) << 1);
        float t00 = 0.f, t01 = 0.f, t10 = 0.f, t11 = 0.f;
        if (r0 < NN)     { float2 tt = *(const float2*)&tb[r0 * 64 + c];      t00 = tt.x; t01 = tt.y; }
        if (r0 + 8 < NN) { float2 tt = *(const float2*)&tb[(r0 + 8) * 64 + c]; t10 = tt.x; t11 = tt.y; }
        sacc[nt][0] = sacc[nt][0] * scale + t00;
        sacc[nt][1] = sacc[nt][1] * scale + t01;
        sacc[nt][2] = sacc[nt][2] * scale + t10;
        sacc[nt][3] = sacc[nt][3] * scale + t11;
    }

    float m0 = -1e30f, m1 = -1e30f;
#pragma unroll
    for (int nt = 0; nt < 8; nt++) {
        m0 = fmaxf(m0, fmaxf(sacc[nt][0], sacc[nt][1]));
        m1 = fmaxf(m1, fmaxf(sacc[nt][2], sacc[nt][3]));
    }
    m0 = fmaxf(m0, __shfl_xor_sync(0xffffffffu, m0, 1));
    m0 = fmaxf(m0, __shfl_xor_sync(0xffffffffu, m0, 2));
    m1 = fmaxf(m1, __shfl_xor_sync(0xffffffffu, m1, 1));
    m1 = fmaxf(m1, __shfl_xor_sync(0xffffffffu, m1, 2));

    float s0 = 0.f, s1 = 0.f;
#pragma unroll
    for (int nt = 0; nt < 8; nt++) {
        sacc[nt][0] = __expf(sacc[nt][0] - m0);
        sacc[nt][1] = __expf(sacc[nt][1] - m0);
        sacc[nt][2] = __expf(sacc[nt][2] - m1);
        sacc[nt][3] = __expf(sacc[nt][3] - m1);
        s0 += sacc[nt][0] + sacc[nt][1];
        s1 += sacc[nt][2] + sacc[nt][3];
    }
    s0 += __shfl_xor_sync(0xffffffffu, s0, 1);
    s0 += __shfl_xor_sync(0xffffffffu, s0, 2);
    s1 += __shfl_xor_sync(0xffffffffu, s1, 1);
    s1 += __shfl_xor_sync(0xffffffffu, s1, 2);
    const float i0 = 1.0f / s0, i1 = 1.0f / s1;

    // ---- O = P V ----
    float oacc[4][4];
#pragma unroll
    for (int i = 0; i < 4; i++)
#pragma unroll
        for (int q = 0; q < 4; q++) oacc[i][q] = 0.f;

    const uint32_t vAddr = vB + ((((lane >> 3) & 1) << 3) + (lane & 7)) * 80
                              + (((lane >> 4) & 1) << 4);
#pragma unroll
    for (int kk = 0; kk < 4; kk++) {
        uint32_t pa[4];
        pa[0] = packbf2(sacc[2 * kk][0] * i0,     sacc[2 * kk][1] * i0);
        pa[1] = packbf2(sacc[2 * kk][2] * i1,     sacc[2 * kk][3] * i1);
        pa[2] = packbf2(sacc[2 * kk + 1][0] * i0, sacc[2 * kk + 1][1] * i0);
        pa[3] = packbf2(sacc[2 * kk + 1][2] * i1, sacc[2 * kk + 1][3] * i1);
        uint32_t b0, b1, b2, b3;
        ldsm4t(b0, b1, b2, b3, vAddr + kk * 16 * 80);
        { uint32_t bv0[2] = {b0, b1}, bv1[2] = {b2, b3};
          mma_bf16(oacc[0], pa, bv0); mma_bf16(oacc[1], pa, bv1); }
        ldsm4t(b0, b1, b2, b3, vAddr + kk * 16 * 80 + 32);
        { uint32_t bv0[2] = {b0, b1}, bv1[2] = {b2, b3};
          mma_bf16(oacc[2], pa, bv0); mma_bf16(oacc[3], pa, bv1); }
    }

    bf16* outB = g_attn + (size_t)w * NN * CC + h * HD;
#pragma unroll
    for (int nt = 0; nt < 4; nt++) {
        const int c = nt * 8 + ((lane & 3) << 1);
        if (r0 < NN)
            *(__nv_bfloat162*)&outB[(size_t)r0 * CC + c] =
                __floats2bfloat162_rn(oacc[nt][0], oacc[nt][1]);
        if (r0 + 8 < NN)
            *(__nv_bfloat162*)&outB[(size_t)(r0 + 8) * CC + c] =
                __floats2bfloat162_rn(oacc[nt][2], oacc[nt][3]);
    }
}

// ---------------- launch ----------------
extern "C" void kernel_launch(void* const* d_in, const int* in_sizes, int n_in,
                              void* d_out, int out_size)
{
    const float* x       = (const float*)d_in[0];
    const float* norm1_g = (const float*)d_in[1];
    const float* norm1_b = (const float*)d_in[2];
    const float* qkv_w   = (const float*)d_in[3];
    const float* qkv_b   = (const float*)d_in[4];
    const float* rel_b   = (const float*)d_in[5];
    const float* proj_w  = (const float*)d_in[6];
    const float* proj_b  = (const float*)d_in[7];
    const float* norm2_g = (const float*)d_in[8];
    const float* norm2_b = (const float*)d_in[9];
    const float* fc1_w   = (const float*)d_in[10];
    const float* fc1_b   = (const float*)d_in[11];
    const float* fc2_w   = (const float*)d_in[12];
    const float* fc2_b   = (const float*)d_in[13];
    float* out = (float*)d_out;

    bf16 *p_xw, *p_qkv, *p_attn, *p_xm, *p_h, *p_wqkv, *p_wprj, *p_wfc1, *p_wfc2;
    float *p_y;
    cudaGetSymbolAddress((void**)&p_xw,   g_xw);
    cudaGetSymbolAddress((void**)&p_qkv,  g_qkv);
    cudaGetSymbolAddress((void**)&p_attn, g_attn);
    cudaGetSymbolAddress((void**)&p_y,    g_y);
    cudaGetSymbolAddress((void**)&p_xm,   g_xm);
    cudaGetSymbolAddress((void**)&p_h,    g_h);
    cudaGetSymbolAddress((void**)&p_wqkv, g_wqkv);
    cudaGetSymbolAddress((void**)&p_wprj, g_wprj);
    cudaGetSymbolAddress((void**)&p_wfc1, g_wfc1);
    cudaGetSymbolAddress((void**)&p_wfc2, g_wfc2);

    const int lnBlocks = TOK / 8;
    dim3 wtb(32, 8);

    // 0) weight transposes + bias/mask tables
    wtrans_kernel<<<dim3(576 / 32, 192 / 32), wtb>>>(qkv_w, p_wqkv, CC, 3 * CC);
    wtrans_kernel<<<dim3(192 / 32, 192 / 32), wtb>>>(proj_w, p_wprj, CC, CC);
    wtrans_kernel<<<dim3(HIDD / 32, 192 / 32), wtb>>>(fc1_w, p_wfc1, CC, HIDD);
    wtrans_kernel<<<dim3(192 / 32, HIDD / 32), wtb>>>(fc2_w, p_wfc2, HIDD, CC);
    tab_kernel<<<24, 256>>>(rel_b);

    // 1) LN1 + shift + window partition (bf16)
    ln_kernel<0><<<lnBlocks, 256>>>(x, norm1_g, norm1_b);

    // 2) QKV gemm [TOK,192]x[192,576] -> bf16
    gemm_bf16<0, 0, true><<<dim3(576 / 64, TOK / 128), 256>>>(
        p_xw, p_wqkv, qkv_b, nullptr, p_qkv, TOK, 3 * CC, CC);

    // 3) tensor-core windowed attention
    attn_mma_kernel<<<(TOK / NN) * NHH, 128>>>();

    // 4) proj gemm + window-reverse/unshift scatter + residual -> g_y (fp32)
    gemm_bf16<0, 2, false><<<dim3(192 / 64, TOK / 128), 256>>>(
        p_attn, p_wprj, proj_b, x, p_y, TOK, CC, CC);

    // 5) LN2 (bf16)
    ln_kernel<1><<<lnBlocks, 256>>>(nullptr, norm2_g, norm2_b);

    // 6) fc1 + exact GELU [TOK,192]x[192,768] -> bf16
    gemm_bf16<1, 0, true><<<dim3(HIDD / 64, TOK / 128), 256>>>(
        p_xm, p_wfc1, fc1_b, nullptr, p_h, TOK, HIDD, CC);

    // 7) fc2 + residual [TOK,768]x[768,192] -> d_out (fp32)
    gemm_bf16<0, 1, false><<<dim3(192 / 64, TOK / 128), 256>>>(
        p_h, p_wfc2, fc2_b, p_y, out, TOK, CC, HIDD);
}

// round 9
// speedup vs baseline: 1.0348x; 1.0319x over previous
#include <cuda_runtime.h>
#include <cuda_bf16.h>
#include <math.h>
#include <stdint.h>

// ---------------- problem constants ----------------
#define BNUM 32
#define HH   56
#define WW   56
#define CC   192
#define NHH  6
#define HD   32
#define WSZ  7
#define SSZ  3
#define NN   49
#define NWIN 64
#define TOK  (BNUM*HH*WW)   // 100352
#define HIDD 768

typedef __nv_bfloat16 bf16;

// ---------------- scratch ----------------
__device__ bf16  g_xw  [(size_t)TOK*CC];      // LN1 out (bf16, windowed)
__device__ bf16  g_qkv [(size_t)TOK*3*CC];    // qkv (bf16)
__device__ bf16  g_attn[(size_t)TOK*CC];      // attention out (bf16, windowed)
__device__ float g_y   [(size_t)TOK*CC];      // x + attn branch (fp32, natural)
__device__ bf16  g_xm  [(size_t)TOK*CC];      // LN2 out (bf16)
__device__ bf16  g_h   [(size_t)TOK*HIDD];    // fc1+GELU out (bf16)
__device__ float g_tab [4*6*49*64];           // bias+mask tables
// transposed bf16 weights [N][K]
__device__ bf16  g_wqkv[(size_t)576*192];
__device__ bf16  g_wprj[(size_t)192*192];
__device__ bf16  g_wfc1[(size_t)HIDD*192];
__device__ bf16  g_wfc2[(size_t)192*HIDD];

// ---------------- PTX helpers ----------------
__device__ __forceinline__ uint32_t smem_u32(const void* p) {
    uint32_t a;
    asm("{ .reg .u64 t; cvta.to.shared.u64 t, %1; cvt.u32.u64 %0, t; }"
        : "=r"(a) : "l"(p));
    return a;
}
__device__ __forceinline__ void cp16(uint32_t s, const void* g) {
    asm volatile("cp.async.cg.shared.global [%0], [%1], 16;" :: "r"(s), "l"(g));
}
#define CP_COMMIT() asm volatile("cp.async.commit_group;" ::: "memory")
__device__ __forceinline__ void ldsm4(uint32_t& r0, uint32_t& r1, uint32_t& r2,
                                      uint32_t& r3, uint32_t a) {
    asm volatile("ldmatrix.sync.aligned.m8n8.x4.shared.b16 {%0,%1,%2,%3}, [%4];"
                 : "=r"(r0), "=r"(r1), "=r"(r2), "=r"(r3) : "r"(a));
}
__device__ __forceinline__ void ldsm4t(uint32_t& r0, uint32_t& r1, uint32_t& r2,
                                       uint32_t& r3, uint32_t a) {
    asm volatile("ldmatrix.sync.aligned.m8n8.x4.trans.shared.b16 {%0,%1,%2,%3}, [%4];"
                 : "=r"(r0), "=r"(r1), "=r"(r2), "=r"(r3) : "r"(a));
}
__device__ __forceinline__ void mma_bf16(float* c, const uint32_t* a, const uint32_t* b) {
    asm volatile(
        "mma.sync.aligned.m16n8k16.row.col.f32.bf16.bf16.f32 "
        "{%0,%1,%2,%3}, {%4,%5,%6,%7}, {%8,%9}, {%0,%1,%2,%3};"
        : "+f"(c[0]), "+f"(c[1]), "+f"(c[2]), "+f"(c[3])
        : "r"(a[0]), "r"(a[1]), "r"(a[2]), "r"(a[3]), "r"(b[0]), "r"(b[1]));
}
__device__ __forceinline__ uint32_t packbf2(float lo, float hi) {
    __nv_bfloat162 h2 = __floats2bfloat162_rn(lo, hi);
    return *reinterpret_cast<uint32_t*>(&h2);
}

// ============ merged prep: 4 weight transposes + bias/mask tables =========
// blocks 0..107    : wqkv  (18 x 6 tiles of 32x32)   W[192,576] -> Wt[576,192]
// blocks 108..143  : wprj  (6 x 6)                   W[192,192]
// blocks 144..287  : wfc1  (24 x 6)                  W[192,768] -> Wt[768,192]
// blocks 288..431  : wfc2  (6 x 24)                  W[768,192] -> Wt[192,768]
// blocks 432..455  : tab
__device__ __forceinline__ void wtrans_tile(const float* W, bf16* Wt,
                                            int K, int N, int bx, int by, int t)
{
    __shared__ float tile[32][33];
    int k0 = by * 32, n0 = bx * 32;
    int tx = t & 31, ty = t >> 5;   // 32 x 8
#pragma unroll
    for (int i = 0; i < 32; i += 8)
        tile[ty + i][tx] = W[(size_t)(k0 + ty + i) * N + n0 + tx];
    __syncthreads();
#pragma unroll
    for (int i = 0; i < 32; i += 8)
        Wt[(size_t)(n0 + ty + i) * K + k0 + tx] = __float2bfloat16(tile[tx][ty + i]);
}

__global__ void prep_kernel(const float* __restrict__ qkv_w,
                            const float* __restrict__ proj_w,
                            const float* __restrict__ fc1_w,
                            const float* __restrict__ fc2_w,
                            const float* __restrict__ rel_bias)
{
    const int b = blockIdx.x;
    const int t = threadIdx.x;
    if (b < 108) {
        wtrans_tile(qkv_w, g_wqkv, CC, 3 * CC, b % 18, b / 18, t);
    } else if (b < 144) {
        int bb = b - 108;
        wtrans_tile(proj_w, g_wprj, CC, CC, bb % 6, bb / 6, t);
    } else if (b < 288) {
        int bb = b - 144;
        wtrans_tile(fc1_w, g_wfc1, CC, HIDD, bb % 24, bb / 24, t);
    } else if (b < 432) {
        int bb = b - 288;
        wtrans_tile(fc2_w, g_wfc2, HIDD, CC, bb % 6, bb / 6, t);
    } else {
        int bh = b - 432;             // 0..23 = mi*6 + h
        int mi = bh / 6, h = bh % 6;
        int eh = mi >> 1, ew = mi & 1;
        for (int idx = t; idx < NN * 64; idx += 256) {
            int i = idx >> 6, j = idx & 63;
            float val;
            if (j >= NN) val = -1e30f;
            else {
                int ih = i / WSZ, iw = i % WSZ, jh = j / WSZ, jw = j % WSZ;
                int dh = ih - jh + (WSZ - 1), dw = iw - jw + (WSZ - 1);
                float bias = rel_bias[(dh * (2 * WSZ - 1) + dw) * NHH + h];
                int ai = eh ? (ih < WSZ - SSZ ? 1 : 2) : 0;
                int bi = ew ? (iw < WSZ - SSZ ? 1 : 2) : 0;
                int aj = eh ? (jh < WSZ - SSZ ? 1 : 2) : 0;
                int bj = ew ? (jw < WSZ - SSZ ? 1 : 2) : 0;
                float mask = ((ai * 3 + bi) != (aj * 3 + bj)) ? -100.0f : 0.0f;
                val = bias + mask;
            }
            g_tab[(size_t)bh * (NN * 64) + idx] = val;
        }
    }
}

// ---------------- LayerNorm (warp per token), bf16 output -----------------
template<int MODE>
__global__ void ln_kernel(const float* __restrict__ x,
                          const float* __restrict__ gamma,
                          const float* __restrict__ beta)
{
    int warp = (blockIdx.x * blockDim.x + threadIdx.x) >> 5;
    int lane = threadIdx.x & 31;
    if (warp >= TOK) return;

    const float* src;
    bf16* dst;
    if (MODE == 0) {
        int tw = warp;
        int w  = tw / NN, n = tw % NN;
        int bb = w / NWIN, wi = w % NWIN;
        int wrow = wi >> 3, wcol = wi & 7;
        int ih = n / WSZ, iw = n % WSZ;
        int gh = wrow * WSZ + ih + SSZ; if (gh >= HH) gh -= HH;
        int gw = wcol * WSZ + iw + SSZ; if (gw >= WW) gw -= WW;
        src = x + ((size_t)bb * HH * WW + (size_t)gh * WW + gw) * CC;
        dst = g_xw + (size_t)tw * CC;
    } else {
        src = g_y + (size_t)warp * CC;
        dst = g_xm + (size_t)warp * CC;
    }

    float v[6];
    float s = 0.f;
#pragma unroll
    for (int k = 0; k < 6; k++) { v[k] = src[lane + 32 * k]; s += v[k]; }
#pragma unroll
    for (int o = 16; o; o >>= 1) s += __shfl_xor_sync(0xffffffffu, s, o);
    float mean = s * (1.0f / CC);
    float vs = 0.f;
#pragma unroll
    for (int k = 0; k < 6; k++) { float d = v[k] - mean; vs += d * d; }
#pragma unroll
    for (int o = 16; o; o >>= 1) vs += __shfl_xor_sync(0xffffffffu, vs, o);
    float inv = rsqrtf(vs * (1.0f / CC) + 1e-5f);
#pragma unroll
    for (int k = 0; k < 6; k++) {
        int c = lane + 32 * k;
        dst[c] = __float2bfloat16((v[k] - mean) * inv * gamma[c] + beta[c]);
    }
}

// ================= bf16 mma GEMM (round-6 proven config) =================
// BM=128, BN=64, BK=32. 256 threads = 8 warps (4m x 2n), warp tile 32x32.
// 2-stage cp.async double buffer.
// RESM: 0 none, 1 residual (natural), 2 scatter window-reverse + residual.
#define SROW 40              // bf16 per smem row (80 B)
#define A_BUF_B (128 * SROW * 2)
#define B_BUF_B (64  * SROW * 2)

template<int ACT, int RESM, bool OBF>
__global__ void __launch_bounds__(256)
gemm_bf16(const bf16* __restrict__ A, const bf16* __restrict__ Wt,
          const float* __restrict__ bias, const float* __restrict__ res,
          void* __restrict__ Cv, int M, int N, int K)
{
    __shared__ __align__(16) bf16 As[2][128 * SROW];
    __shared__ __align__(16) bf16 Bs[2][64 * SROW];

    const int t    = threadIdx.x;
    const int lane = t & 31;
    const int wid  = t >> 5;
    const int wm   = wid & 3;
    const int wn   = wid >> 2;
    const int m0   = blockIdx.y << 7;
    const int n0   = blockIdx.x << 6;

    const uint32_t asB = smem_u32(As);
    const uint32_t bsB = smem_u32(Bs);

    const int T = K >> 5;
    const int a_row = t >> 2, a_kc = (t & 3) << 3;

    auto load_tiles = [&](int kt, int b) {
        const int k0 = kt << 5;
        uint32_t aD = asB + b * A_BUF_B;
        cp16(aD + a_row * 80 + (a_kc << 1),
             A + (size_t)(m0 + a_row) * K + k0 + a_kc);
        cp16(aD + (a_row + 64) * 80 + (a_kc << 1),
             A + (size_t)(m0 + a_row + 64) * K + k0 + a_kc);
        uint32_t bD = bsB + b * B_BUF_B;
        cp16(bD + a_row * 80 + (a_kc << 1),
             Wt + (size_t)(n0 + a_row) * K + k0 + a_kc);
        CP_COMMIT();
    };

    float acc[2][4][4];
#pragma unroll
    for (int i = 0; i < 2; i++)
#pragma unroll
        for (int j = 0; j < 4; j++)
#pragma unroll
            for (int q = 0; q < 4; q++) acc[i][j][q] = 0.f;

    const uint32_t aFrag = (wm * 32 + (lane & 15)) * 80 + ((lane >> 4) << 4);
    const uint32_t bFrag = (wn * 32 + (lane & 7) + (((lane >> 4) & 1) << 3)) * 80
                           + (((lane >> 3) & 1) << 4);

    load_tiles(0, 0);

    for (int kt = 0; kt < T; kt++) {
        const int b = kt & 1;
        if (kt + 1 < T) {
            load_tiles(kt + 1, b ^ 1);
            asm volatile("cp.async.wait_group 1;" ::: "memory");
        } else {
            asm volatile("cp.async.wait_group 0;" ::: "memory");
        }
        __syncthreads();

        const uint32_t aB = asB + b * A_BUF_B + aFrag;
        const uint32_t bB = bsB + b * B_BUF_B + bFrag;
#pragma unroll
        for (int kk = 0; kk < 2; kk++) {
            uint32_t av[2][4], bv[4][2];
            ldsm4(av[0][0], av[0][1], av[0][2], av[0][3], aB + kk * 32);
            ldsm4(av[1][0], av[1][1], av[1][2], av[1][3], aB + 16 * 80 + kk * 32);
            ldsm4(bv[0][0], bv[0][1], bv[1][0], bv[1][1], bB + kk * 32);
            ldsm4(bv[2][0], bv[2][1], bv[3][0], bv[3][1], bB + 16 * 80 + kk * 32);
#pragma unroll
            for (int mt = 0; mt < 2; mt++)
#pragma unroll
                for (int nt = 0; nt < 4; nt++)
                    mma_bf16(acc[mt][nt], av[mt], bv[nt]);
        }
        __syncthreads();
    }

    // ---------------- epilogue ----------------
    const int colBase = n0 + wn * 32 + ((lane & 3) << 1);
    const int rowBase = m0 + wm * 32 + (lane >> 2);
#pragma unroll
    for (int mt = 0; mt < 2; mt++) {
#pragma unroll
        for (int half = 0; half < 2; half++) {
            const int r = rowBase + mt * 16 + half * 8;
            size_t outRow = (size_t)r;
            if (RESM == 2) {
                int wq = r / NN, nq = r % NN;
                int bq = wq >> 6, wiq = wq & 63;
                int gh = (wiq >> 3) * WSZ + nq / WSZ + SSZ; if (gh >= HH) gh -= HH;
                int gw = (wiq & 7)  * WSZ + nq % WSZ + SSZ; if (gw >= WW) gw -= WW;
                outRow = (size_t)bq * (HH * WW) + gh * WW + gw;
            }
            const float* Rrow = res + outRow * N;
#pragma unroll
            for (int nt = 0; nt < 4; nt++) {
                const int c0 = colBase + nt * 8;
                float v0 = acc[mt][nt][half * 2 + 0] + bias[c0];
                float v1 = acc[mt][nt][half * 2 + 1] + bias[c0 + 1];
                if (ACT == 1) {
                    v0 = 0.5f * v0 * (1.0f + erff(v0 * 0.70710678118654752f));
                    v1 = 0.5f * v1 * (1.0f + erff(v1 * 0.70710678118654752f));
                }
                if (RESM != 0) { v0 += Rrow[c0]; v1 += Rrow[c0 + 1]; }
                if (OBF) {
                    bf16* Crow = (bf16*)Cv + outRow * N;
                    *(__nv_bfloat162*)&Crow[c0] = __floats2bfloat162_rn(v0, v1);
                } else {
                    float* Crow = (float*)Cv + outRow * N;
                    float2 o; o.x = v0; o.y = v1;
                    *(float2*)&Crow[c0] = o;
                }
            }
        }
    }
}

// ================= tensor-core windowed attention: 2 heads / block ========
// 256 threads = 8 warps. Warps 0-3 -> head hp*2, warps 4-7 -> head hp*2+1.
#define ATT_STG (64 * SROW)     // bf16 elements per head stage (5120 B)

__global__ void __launch_bounds__(256)
attn_mma_kernel()
{
    __shared__ __align__(16) bf16 Qs[2][ATT_STG];
    __shared__ __align__(16) bf16 Ks[2][ATT_STG];
    __shared__ __align__(16) bf16 Vs[2][ATT_STG];

    const int blk = blockIdx.x;
    const int w = blk / 3, hp = blk % 3;     // window, head-pair
    const int t = threadIdx.x;
    const int lane = t & 31;
    const int wid = t >> 5;
    const int hs  = wid >> 2;                // head within pair for this warp
    const int mt  = wid & 3;                 // m-tile within head
    const int h   = hp * 2 + hs;

    const uint32_t qB = smem_u32(Qs) + hs * (ATT_STG * 2);
    const uint32_t kB = smem_u32(Ks) + hs * (ATT_STG * 2);
    const uint32_t vB = smem_u32(Vs) + hs * (ATT_STG * 2);

    // zero padding rows 49..63 for both heads (stride 40 bf16 = 20 u32)
    for (int i = t; i < 2 * 15 * 20; i += 256) {
        int hsel = i / 300, j = i % 300;
        int off = hsel * (ATT_STG / 2) + (49 + j / 20) * 20 + (j % 20);
        ((uint32_t*)Qs)[off] = 0;
        ((uint32_t*)Ks)[off] = 0;
        ((uint32_t*)Vs)[off] = 0;
    }

    // load Q,K,V for 2 heads: 2 x 49 rows x 4 chunks of 16B
    const bf16* base = g_qkv + (size_t)w * NN * (3 * CC) + hp * 2 * HD;
    for (int i = t; i < 2 * NN * 4; i += 256) {
        int hsel = i / (NN * 4), j = i % (NN * 4);
        int r = j >> 2, c = (j & 3) << 3;
        const bf16* src = base + (size_t)r * (3 * CC) + hsel * HD + c;
        uint32_t d = hsel * (ATT_STG * 2) + r * 80 + (c << 1);
        cp16(smem_u32(Qs) + d, src);
        cp16(smem_u32(Ks) + d, src + CC);
        cp16(smem_u32(Vs) + d, src + 2 * CC);
    }
    CP_COMMIT();
    asm volatile("cp.async.wait_group 0;" ::: "memory");
    __syncthreads();

    // ---- S = Q K^T ----
    float sacc[8][4];
#pragma unroll
    for (int i = 0; i < 8; i++)
#pragma unroll
        for (int q = 0; q < 4; q++) sacc[i][q] = 0.f;

    const uint32_t aAddr = qB + (mt * 16 + (lane & 15)) * 80 + ((lane >> 4) << 4);
    const uint32_t bAddr = kB + ((lane & 7) + (((lane >> 4) & 1) << 3)) * 80
                              + (((lane >> 3) & 1) << 4);
#pragma unroll
    for (int kk = 0; kk < 2; kk++) {
        uint32_t av[4];
        ldsm4(av[0], av[1], av[2], av[3], aAddr + kk * 32);
#pragma unroll
        for (int ng = 0; ng < 4; ng++) {
            uint32_t b0, b1, b2, b3;
            ldsm4(b0, b1, b2, b3, bAddr + ng * 16 * 80 + kk * 32);
            uint32_t bv0[2] = {b0, b1}, bv1[2] = {b2, b3};
            mma_bf16(sacc[2 * ng],     av, bv0);
            mma_bf16(sacc[2 * ng + 1], av, bv1);
        }
    }

    // ---- scale + table + softmax in fragments ----
    const int wi = w & (NWIN - 1);
    const int mi = (((wi >> 3) == 7) ? 2 : 0) + (((wi & 7) == 7) ? 1 : 0);
    const float* tb = g_tab + (size_t)(mi * NHH + h) * (NN * 64);
    const int r0 = mt * 16 + (lane >> 2);
    const float scale = 0.17677669529663687f;

#pragma unroll
    for (int nt = 0; nt < 8; nt++) {
        const int c = nt * 8 + ((lane & 3) << 1);
        float t00 = 0.f, t01 = 0.f, t10 = 0.f, t11 = 0.f;
        if (r0 < NN)     { float2 tt = *(const float2*)&tb[r0 * 64 + c];      t00 = tt.x; t01 = tt.y; }
        if (r0 + 8 < NN) { float2 tt = *(const float2*)&tb[(r0 + 8) * 64 + c]; t10 = tt.x; t11 = tt.y; }
        sacc[nt][0] = sacc[nt][0] * scale + t00;
        sacc[nt][1] = sacc[nt][1] * scale + t01;
        sacc[nt][2] = sacc[nt][2] * scale + t10;
        sacc[nt][3] = sacc[nt][3] * scale + t11;
    }

    float m0 = -1e30f, m1 = -1e30f;
#pragma unroll
    for (int nt = 0; nt < 8; nt++) {
        m0 = fmaxf(m0, fmaxf(sacc[nt][0], sacc[nt][1]));
        m1 = fmaxf(m1, fmaxf(sacc[nt][2], sacc[nt][3]));
    }
    m0 = fmaxf(m0, __shfl_xor_sync(0xffffffffu, m0, 1));
    m0 = fmaxf(m0, __shfl_xor_sync(0xffffffffu, m0, 2));
    m1 = fmaxf(m1, __shfl_xor_sync(0xffffffffu, m1, 1));
    m1 = fmaxf(m1, __shfl_xor_sync(0xffffffffu, m1, 2));

    float s0 = 0.f, s1 = 0.f;
#pragma unroll
    for (int nt = 0; nt < 8; nt++) {
        sacc[nt][0] = __expf(sacc[nt][0] - m0);
        sacc[nt][1] = __expf(sacc[nt][1] - m0);
        sacc[nt][2] = __expf(sacc[nt][2] - m1);
        sacc[nt][3] = __expf(sacc[nt][3] - m1);
        s0 += sacc[nt][0] + sacc[nt][1];
        s1 += sacc[nt][2] + sacc[nt][3];
    }
    s0 += __shfl_xor_sync(0xffffffffu, s0, 1);
    s0 += __shfl_xor_sync(0xffffffffu, s0, 2);
    s1 += __shfl_xor_sync(0xffffffffu, s1, 1);
    s1 += __shfl_xor_sync(0xffffffffu, s1, 2);
    const float i0 = 1.0f / s0, i1 = 1.0f / s1;

    // ---- O = P V ----
    float oacc[4][4];
#pragma unroll
    for (int i = 0; i < 4; i++)
#pragma unroll
        for (int q = 0; q < 4; q++) oacc[i][q] = 0.f;

    const uint32_t vAddr = vB + ((((lane >> 3) & 1) << 3) + (lane & 7)) * 80
                              + (((lane >> 4) & 1) << 4);
#pragma unroll
    for (int kk = 0; kk < 4; kk++) {
        uint32_t pa[4];
        pa[0] = packbf2(sacc[2 * kk][0] * i0,     sacc[2 * kk][1] * i0);
        pa[1] = packbf2(sacc[2 * kk][2] * i1,     sacc[2 * kk][3] * i1);
        pa[2] = packbf2(sacc[2 * kk + 1][0] * i0, sacc[2 * kk + 1][1] * i0);
        pa[3] = packbf2(sacc[2 * kk + 1][2] * i1, sacc[2 * kk + 1][3] * i1);
        uint32_t b0, b1, b2, b3;
        ldsm4t(b0, b1, b2, b3, vAddr + kk * 16 * 80);
        { uint32_t bv0[2] = {b0, b1}, bv1[2] = {b2, b3};
          mma_bf16(oacc[0], pa, bv0); mma_bf16(oacc[1], pa, bv1); }
        ldsm4t(b0, b1, b2, b3, vAddr + kk * 16 * 80 + 32);
        { uint32_t bv0[2] = {b0, b1}, bv1[2] = {b2, b3};
          mma_bf16(oacc[2], pa, bv0); mma_bf16(oacc[3], pa, bv1); }
    }

    bf16* outB = g_attn + (size_t)w * NN * CC + h * HD;
#pragma unroll
    for (int nt = 0; nt < 4; nt++) {
        const int c = nt * 8 + ((lane & 3) << 1);
        if (r0 < NN)
            *(__nv_bfloat162*)&outB[(size_t)r0 * CC + c] =
                __floats2bfloat162_rn(oacc[nt][0], oacc[nt][1]);
        if (r0 + 8 < NN)
            *(__nv_bfloat162*)&outB[(size_t)(r0 + 8) * CC + c] =
                __floats2bfloat162_rn(oacc[nt][2], oacc[nt][3]);
    }
}

// ---------------- launch ----------------
extern "C" void kernel_launch(void* const* d_in, const int* in_sizes, int n_in,
                              void* d_out, int out_size)
{
    const float* x       = (const float*)d_in[0];
    const float* norm1_g = (const float*)d_in[1];
    const float* norm1_b = (const float*)d_in[2];
    const float* qkv_w   = (const float*)d_in[3];
    const float* qkv_b   = (const float*)d_in[4];
    const float* rel_b   = (const float*)d_in[5];
    const float* proj_w  = (const float*)d_in[6];
    const float* proj_b  = (const float*)d_in[7];
    const float* norm2_g = (const float*)d_in[8];
    const float* norm2_b = (const float*)d_in[9];
    const float* fc1_w   = (const float*)d_in[10];
    const float* fc1_b   = (const float*)d_in[11];
    const float* fc2_w   = (const float*)d_in[12];
    const float* fc2_b   = (const float*)d_in[13];
    float* out = (float*)d_out;

    bf16 *p_xw, *p_qkv, *p_attn, *p_xm, *p_h, *p_wqkv, *p_wprj, *p_wfc1, *p_wfc2;
    float *p_y;
    cudaGetSymbolAddress((void**)&p_xw,   g_xw);
    cudaGetSymbolAddress((void**)&p_qkv,  g_qkv);
    cudaGetSymbolAddress((void**)&p_attn, g_attn);
    cudaGetSymbolAddress((void**)&p_y,    g_y);
    cudaGetSymbolAddress((void**)&p_xm,   g_xm);
    cudaGetSymbolAddress((void**)&p_h,    g_h);
    cudaGetSymbolAddress((void**)&p_wqkv, g_wqkv);
    cudaGetSymbolAddress((void**)&p_wprj, g_wprj);
    cudaGetSymbolAddress((void**)&p_wfc1, g_wfc1);
    cudaGetSymbolAddress((void**)&p_wfc2, g_wfc2);

    const int lnBlocks = TOK / 8;

    // 0) merged prep: all weight transposes + tables in ONE launch
    prep_kernel<<<456, 256>>>(qkv_w, proj_w, fc1_w, fc2_w, rel_b);

    // 1) LN1 + shift + window partition (bf16)
    ln_kernel<0><<<lnBlocks, 256>>>(x, norm1_g, norm1_b);

    // 2) QKV gemm [TOK,192]x[192,576] -> bf16
    gemm_bf16<0, 0, true><<<dim3(576 / 64, TOK / 128), 256>>>(
        p_xw, p_wqkv, qkv_b, nullptr, p_qkv, TOK, 3 * CC, CC);

    // 3) tensor-core windowed attention (2 heads / block)
    attn_mma_kernel<<<(TOK / NN) * 3, 256>>>();

    // 4) proj gemm + window-reverse/unshift scatter + residual -> g_y (fp32)
    gemm_bf16<0, 2, false><<<dim3(192 / 64, TOK / 128), 256>>>(
        p_attn, p_wprj, proj_b, x, p_y, TOK, CC, CC);

    // 5) LN2 (bf16)
    ln_kernel<1><<<lnBlocks, 256>>>(nullptr, norm2_g, norm2_b);

    // 6) fc1 + exact GELU [TOK,192]x[192,768] -> bf16
    gemm_bf16<1, 0, true><<<dim3(HIDD / 64, TOK / 128), 256>>>(
        p_xm, p_wfc1, fc1_b, nullptr, p_h, TOK, HIDD, CC);

    // 7) fc2 + residual [TOK,768]x[768,192] -> d_out (fp32)
    gemm_bf16<0, 1, false><<<dim3(192 / 64, TOK / 128), 256>>>(
        p_h, p_wfc2, fc2_b, p_y, out, TOK, CC, HIDD);
}

// round 12
// speedup vs baseline: 1.0696x; 1.0337x over previous
#include <cuda_runtime.h>
#include <cuda_bf16.h>
#include <math.h>
#include <stdint.h>

// ---------------- problem constants ----------------
#define BNUM 32
#define HH   56
#define WW   56
#define CC   192
#define NHH  6
#define HD   32
#define WSZ  7
#define SSZ  3
#define NN   49
#define NWIN 64
#define TOK  (BNUM*HH*WW)   // 100352
#define HIDD 768

typedef __nv_bfloat16 bf16;

// ---------------- scratch ----------------
__device__ bf16  g_xw  [(size_t)TOK*CC];
__device__ bf16  g_qkv [(size_t)TOK*3*CC];
__device__ bf16  g_attn[(size_t)TOK*CC];
__device__ float g_y   [(size_t)TOK*CC];
__device__ bf16  g_xm  [(size_t)TOK*CC];
__device__ bf16  g_h   [(size_t)TOK*HIDD];
__device__ float g_tab [4*6*49*64];
__device__ bf16  g_wqkv[(size_t)576*192];
__device__ bf16  g_wprj[(size_t)192*192];
__device__ bf16  g_wfc1[(size_t)HIDD*192];
__device__ bf16  g_wfc2[(size_t)192*HIDD];

// ---------------- PTX helpers ----------------
__device__ __forceinline__ uint32_t smem_u32(const void* p) {
    uint32_t a;
    asm("{ .reg .u64 t; cvta.to.shared.u64 t, %1; cvt.u32.u64 %0, t; }"
        : "=r"(a) : "l"(p));
    return a;
}
__device__ __forceinline__ void cp16(uint32_t s, const void* g) {
    asm volatile("cp.async.cg.shared.global [%0], [%1], 16;" :: "r"(s), "l"(g));
}
#define CP_COMMIT() asm volatile("cp.async.commit_group;" ::: "memory")
__device__ __forceinline__ void ldsm4(uint32_t& r0, uint32_t& r1, uint32_t& r2,
                                      uint32_t& r3, uint32_t a) {
    asm volatile("ldmatrix.sync.aligned.m8n8.x4.shared.b16 {%0,%1,%2,%3}, [%4];"
                 : "=r"(r0), "=r"(r1), "=r"(r2), "=r"(r3) : "r"(a));
}
__device__ __forceinline__ void ldsm4t(uint32_t& r0, uint32_t& r1, uint32_t& r2,
                                       uint32_t& r3, uint32_t a) {
    asm volatile("ldmatrix.sync.aligned.m8n8.x4.trans.shared.b16 {%0,%1,%2,%3}, [%4];"
                 : "=r"(r0), "=r"(r1), "=r"(r2), "=r"(r3) : "r"(a));
}
__device__ __forceinline__ void mma_bf16(float* c, const uint32_t* a, const uint32_t* b) {
    asm volatile(
        "mma.sync.aligned.m16n8k16.row.col.f32.bf16.bf16.f32 "
        "{%0,%1,%2,%3}, {%4,%5,%6,%7}, {%8,%9}, {%0,%1,%2,%3};"
        : "+f"(c[0]), "+f"(c[1]), "+f"(c[2]), "+f"(c[3])
        : "r"(a[0]), "r"(a[1]), "r"(a[2]), "r"(a[3]), "r"(b[0]), "r"(b[1]));
}
__device__ __forceinline__ uint32_t packbf2(float lo, float hi) {
    __nv_bfloat162 h2 = __floats2bfloat162_rn(lo, hi);
    return *reinterpret_cast<uint32_t*>(&h2);
}

// ============ merged prep: 4 weight transposes + bias/mask tables =========
__device__ __forceinline__ void wtrans_tile(const float* W, bf16* Wt,
                                            int K, int N, int bx, int by, int t)
{
    __shared__ float tile[32][33];
    int k0 = by * 32, n0 = bx * 32;
    int tx = t & 31, ty = t >> 5;   // 32 x 8
#pragma unroll
    for (int i = 0; i < 32; i += 8)
        tile[ty + i][tx] = W[(size_t)(k0 + ty + i) * N + n0 + tx];
    __syncthreads();
#pragma unroll
    for (int i = 0; i < 32; i += 8)
        Wt[(size_t)(n0 + ty + i) * K + k0 + tx] = __float2bfloat16(tile[tx][ty + i]);
}

__global__ void prep_kernel(const float* __restrict__ qkv_w,
                            const float* __restrict__ proj_w,
                            const float* __restrict__ fc1_w,
                            const float* __restrict__ fc2_w,
                            const float* __restrict__ rel_bias)
{
    const int b = blockIdx.x;
    const int t = threadIdx.x;
    if (b < 108) {
        wtrans_tile(qkv_w, g_wqkv, CC, 3 * CC, b % 18, b / 18, t);
    } else if (b < 144) {
        int bb = b - 108;
        wtrans_tile(proj_w, g_wprj, CC, CC, bb % 6, bb / 6, t);
    } else if (b < 288) {
        int bb = b - 144;
        wtrans_tile(fc1_w, g_wfc1, CC, HIDD, bb % 24, bb / 24, t);
    } else if (b < 432) {
        int bb = b - 288;
        wtrans_tile(fc2_w, g_wfc2, HIDD, CC, bb % 6, bb / 6, t);
    } else {
        int bh = b - 432;             // 0..23 = mi*6 + h
        int mi = bh / 6, h = bh % 6;
        int eh = mi >> 1, ew = mi & 1;
        for (int idx = t; idx < NN * 64; idx += 256) {
            int i = idx >> 6, j = idx & 63;
            float val;
            if (j >= NN) val = -1e30f;
            else {
                int ih = i / WSZ, iw = i % WSZ, jh = j / WSZ, jw = j % WSZ;
                int dh = ih - jh + (WSZ - 1), dw = iw - jw + (WSZ - 1);
                float bias = rel_bias[(dh * (2 * WSZ - 1) + dw) * NHH + h];
                int ai = eh ? (ih < WSZ - SSZ ? 1 : 2) : 0;
                int bi = ew ? (iw < WSZ - SSZ ? 1 : 2) : 0;
                int aj = eh ? (jh < WSZ - SSZ ? 1 : 2) : 0;
                int bj = ew ? (jw < WSZ - SSZ ? 1 : 2) : 0;
                float mask = ((ai * 3 + bi) != (aj * 3 + bj)) ? -100.0f : 0.0f;
                val = bias + mask;
            }
            g_tab[(size_t)bh * (NN * 64) + idx] = val;
        }
    }
}

// ---------------- LayerNorm (warp per token), bf16 output -----------------
template<int MODE>
__global__ void ln_kernel(const float* __restrict__ x,
                          const float* __restrict__ gamma,
                          const float* __restrict__ beta)
{
    int warp = (blockIdx.x * blockDim.x + threadIdx.x) >> 5;
    int lane = threadIdx.x & 31;
    if (warp >= TOK) return;

    const float* src;
    bf16* dst;
    if (MODE == 0) {
        int tw = warp;
        int w  = tw / NN, n = tw % NN;
        int bb = w / NWIN, wi = w % NWIN;
        int wrow = wi >> 3, wcol = wi & 7;
        int ih = n / WSZ, iw = n % WSZ;
        int gh = wrow * WSZ + ih + SSZ; if (gh >= HH) gh -= HH;
        int gw = wcol * WSZ + iw + SSZ; if (gw >= WW) gw -= WW;
        src = x + ((size_t)bb * HH * WW + (size_t)gh * WW + gw) * CC;
        dst = g_xw + (size_t)tw * CC;
    } else {
        src = g_y + (size_t)warp * CC;
        dst = g_xm + (size_t)warp * CC;
    }

    float v[6];
    float s = 0.f;
#pragma unroll
    for (int k = 0; k < 6; k++) { v[k] = src[lane + 32 * k]; s += v[k]; }
#pragma unroll
    for (int o = 16; o; o >>= 1) s += __shfl_xor_sync(0xffffffffu, s, o);
    float mean = s * (1.0f / CC);
    float vs = 0.f;
#pragma unroll
    for (int k = 0; k < 6; k++) { float d = v[k] - mean; vs += d * d; }
#pragma unroll
    for (int o = 16; o; o >>= 1) vs += __shfl_xor_sync(0xffffffffu, vs, o);
    float inv = rsqrtf(vs * (1.0f / CC) + 1e-5f);
#pragma unroll
    for (int k = 0; k < 6; k++) {
        int c = lane + 32 * k;
        dst[c] = __float2bfloat16((v[k] - mean) * inv * gamma[c] + beta[c]);
    }
}

// ================= bf16 mma GEMM =================
// BM=128, BN=64, BK=32. 128 threads = 4 warps (4m x 1n), warp tile 32x64.
// A fetched once per warp (no cross-warp A redundancy): 48 ldsm4/K-tile vs 64.
// 2-stage cp.async double buffer.
// RESM: 0 none, 1 residual (natural), 2 scatter window-reverse + residual.
#define SROW 40              // bf16 per smem row (80 B)
#define A_BUF_B (128 * SROW * 2)
#define B_BUF_B (64  * SROW * 2)

template<int ACT, int RESM, bool OBF>
__global__ void __launch_bounds__(128)
gemm_bf16(const bf16* __restrict__ A, const bf16* __restrict__ Wt,
          const float* __restrict__ bias, const float* __restrict__ res,
          void* __restrict__ Cv, int M, int N, int K)
{
    __shared__ __align__(16) bf16 As[2][128 * SROW];
    __shared__ __align__(16) bf16 Bs[2][64 * SROW];

    const int t    = threadIdx.x;
    const int lane = t & 31;
    const int wid  = t >> 5;          // warp = m-group
    const int m0   = blockIdx.y << 7;
    const int n0   = blockIdx.x << 6;

    const uint32_t asB = smem_u32(As);
    const uint32_t bsB = smem_u32(Bs);

    const int T = K >> 5;

    auto load_tiles = [&](int kt, int b) {
        const int k0 = kt << 5;
        uint32_t aD = asB + b * A_BUF_B;
#pragma unroll
        for (int r = 0; r < 4; r++) {
            int i = t + 128 * r;
            int row = i >> 2, c = i & 3;
            cp16(aD + row * 80 + (c << 4),
                 A + (size_t)(m0 + row) * K + k0 + (c << 3));
        }
        uint32_t bD = bsB + b * B_BUF_B;
#pragma unroll
        for (int r = 0; r < 2; r++) {
            int i = t + 128 * r;
            int row = i >> 2, c = i & 3;
            cp16(bD + row * 80 + (c << 4),
                 Wt + (size_t)(n0 + row) * K + k0 + (c << 3));
        }
        CP_COMMIT();
    };

    float acc[2][8][4];
#pragma unroll
    for (int i = 0; i < 2; i++)
#pragma unroll
        for (int j = 0; j < 8; j++)
#pragma unroll
            for (int q = 0; q < 4; q++) acc[i][j][q] = 0.f;

    const uint32_t aFrag = (wid * 32 + (lane & 15)) * 80 + ((lane >> 4) << 4);
    const uint32_t bFrag = ((lane & 7) + (((lane >> 4) & 1) << 3)) * 80
                           + (((lane >> 3) & 1) << 4);

    load_tiles(0, 0);

    for (int kt = 0; kt < T; kt++) {
        const int b = kt & 1;
        if (kt + 1 < T) {
            load_tiles(kt + 1, b ^ 1);
            asm volatile("cp.async.wait_group 1;" ::: "memory");
        } else {
            asm volatile("cp.async.wait_group 0;" ::: "memory");
        }
        __syncthreads();

        const uint32_t aB = asB + b * A_BUF_B + aFrag;
        const uint32_t bB = bsB + b * B_BUF_B + bFrag;
#pragma unroll
        for (int kk = 0; kk < 2; kk++) {
            uint32_t av[2][4], bv[8][2];
            ldsm4(av[0][0], av[0][1], av[0][2], av[0][3], aB + kk * 32);
            ldsm4(av[1][0], av[1][1], av[1][2], av[1][3], aB + 16 * 80 + kk * 32);
#pragma unroll
            for (int g = 0; g < 4; g++)
                ldsm4(bv[2 * g][0], bv[2 * g][1], bv[2 * g + 1][0], bv[2 * g + 1][1],
                      bB + g * 16 * 80 + kk * 32);
#pragma unroll
            for (int mt = 0; mt < 2; mt++)
#pragma unroll
                for (int nt = 0; nt < 8; nt++)
                    mma_bf16(acc[mt][nt], av[mt], bv[nt]);
        }
        __syncthreads();
    }

    // ---------------- epilogue ----------------
    const int colBase = n0 + ((lane & 3) << 1);
    const int rowBase = m0 + wid * 32 + (lane >> 2);
#pragma unroll
    for (int mt = 0; mt < 2; mt++) {
#pragma unroll
        for (int half = 0; half < 2; half++) {
            const int r = rowBase + mt * 16 + half * 8;
            size_t outRow = (size_t)r;
            if (RESM == 2) {
                int wq = r / NN, nq = r % NN;
                int bq = wq >> 6, wiq = wq & 63;
                int gh = (wiq >> 3) * WSZ + nq / WSZ + SSZ; if (gh >= HH) gh -= HH;
                int gw = (wiq & 7)  * WSZ + nq % WSZ + SSZ; if (gw >= WW) gw -= WW;
                outRow = (size_t)bq * (HH * WW) + gh * WW + gw;
            }
            const float* Rrow = res + outRow * N;
#pragma unroll
            for (int nt = 0; nt < 8; nt++) {
                const int c0 = colBase + nt * 8;
                float v0 = acc[mt][nt][half * 2 + 0] + bias[c0];
                float v1 = acc[mt][nt][half * 2 + 1] + bias[c0 + 1];
                if (ACT == 1) {
                    v0 = 0.5f * v0 * (1.0f + erff(v0 * 0.70710678118654752f));
                    v1 = 0.5f * v1 * (1.0f + erff(v1 * 0.70710678118654752f));
                }
                if (RESM != 0) { v0 += Rrow[c0]; v1 += Rrow[c0 + 1]; }
                if (OBF) {
                    bf16* Crow = (bf16*)Cv + outRow * N;
                    *(__nv_bfloat162*)&Crow[c0] = __floats2bfloat162_rn(v0, v1);
                } else {
                    float* Crow = (float*)Cv + outRow * N;
                    float2 o; o.x = v0; o.y = v1;
                    *(float2*)&Crow[c0] = o;
                }
            }
        }
    }
}

// ================= tensor-core windowed attention: 2 heads / block ========
#define ATT_STG (64 * SROW)

__global__ void __launch_bounds__(256)
attn_mma_kernel()
{
    __shared__ __align__(16) bf16 Qs[2][ATT_STG];
    __shared__ __align__(16) bf16 Ks[2][ATT_STG];
    __shared__ __align__(16) bf16 Vs[2][ATT_STG];

    const int blk = blockIdx.x;
    const int w = blk / 3, hp = blk % 3;
    const int t = threadIdx.x;
    const int lane = t & 31;
    const int wid = t >> 5;
    const int hs  = wid >> 2;
    const int mt  = wid & 3;
    const int h   = hp * 2 + hs;

    const uint32_t qB = smem_u32(Qs) + hs * (ATT_STG * 2);
    const uint32_t kB = smem_u32(Ks) + hs * (ATT_STG * 2);
    const uint32_t vB = smem_u32(Vs) + hs * (ATT_STG * 2);

    for (int i = t; i < 2 * 15 * 20; i += 256) {
        int hsel = i / 300, j = i % 300;
        int off = hsel * (ATT_STG / 2) + (49 + j / 20) * 20 + (j % 20);
        ((uint32_t*)Qs)[off] = 0;
        ((uint32_t*)Ks)[off] = 0;
        ((uint32_t*)Vs)[off] = 0;
    }

    const bf16* base = g_qkv + (size_t)w * NN * (3 * CC) + hp * 2 * HD;
    for (int i = t; i < 2 * NN * 4; i += 256) {
        int hsel = i / (NN * 4), j = i % (NN * 4);
        int r = j >> 2, c = (j & 3) << 3;
        const bf16* src = base + (size_t)r * (3 * CC) + hsel * HD + c;
        uint32_t d = hsel * (ATT_STG * 2) + r * 80 + (c << 1);
        cp16(smem_u32(Qs) + d, src);
        cp16(smem_u32(Ks) + d, src + CC);
        cp16(smem_u32(Vs) + d, src + 2 * CC);
    }
    CP_COMMIT();
    asm volatile("cp.async.wait_group 0;" ::: "memory");
    __syncthreads();

    // ---- S = Q K^T ----
    float sacc[8][4];
#pragma unroll
    for (int i = 0; i < 8; i++)
#pragma unroll
        for (int q = 0; q < 4; q++) sacc[i][q] = 0.f;

    const uint32_t aAddr = qB + (mt * 16 + (lane & 15)) * 80 + ((lane >> 4) << 4);
    const uint32_t bAddr = kB + ((lane & 7) + (((lane >> 4) & 1) << 3)) * 80
                              + (((lane >> 3) & 1) << 4);
#pragma unroll
    for (int kk = 0; kk < 2; kk++) {
        uint32_t av[4];
        ldsm4(av[0], av[1], av[2], av[3], aAddr + kk * 32);
#pragma unroll
        for (int ng = 0; ng < 4; ng++) {
            uint32_t b0, b1, b2, b3;
            ldsm4(b0, b1, b2, b3, bAddr + ng * 16 * 80 + kk * 32);
            uint32_t bv0[2] = {b0, b1}, bv1[2] = {b2, b3};
            mma_bf16(sacc[2 * ng],     av, bv0);
            mma_bf16(sacc[2 * ng + 1], av, bv1);
        }
    }

    // ---- scale + table + softmax in fragments ----
    const int wi = w & (NWIN - 1);
    const int mi = (((wi >> 3) == 7) ? 2 : 0) + (((wi & 7) == 7) ? 1 : 0);
    const float* tb = g_tab + (size_t)(mi * NHH + h) * (NN * 64);
    const int r0 = mt * 16 + (lane >> 2);
    const float scale = 0.17677669529663687f;

#pragma unroll
    for (int nt = 0; nt < 8; nt++) {
        const int c = nt * 8 + ((lane & 3) << 1);
        float t00 = 0.f, t01 = 0.f, t10 = 0.f, t11 = 0.f;
        if (r0 < NN)     { float2 tt = *(const float2*)&tb[r0 * 64 + c];      t00 = tt.x; t01 = tt.y; }
        if (r0 + 8 < NN) { float2 tt = *(const float2*)&tb[(r0 + 8) * 64 + c]; t10 = tt.x; t11 = tt.y; }
        sacc[nt][0] = sacc[nt][0] * scale + t00;
        sacc[nt][1] = sacc[nt][1] * scale + t01;
        sacc[nt][2] = sacc[nt][2] * scale + t10;
        sacc[nt][3] = sacc[nt][3] * scale + t11;
    }

    float m0 = -1e30f, m1 = -1e30f;
#pragma unroll
    for (int nt = 0; nt < 8; nt++) {
        m0 = fmaxf(m0, fmaxf(sacc[nt][0], sacc[nt][1]));
        m1 = fmaxf(m1, fmaxf(sacc[nt][2], sacc[nt][3]));
    }
    m0 = fmaxf(m0, __shfl_xor_sync(0xffffffffu, m0, 1));
    m0 = fmaxf(m0, __shfl_xor_sync(0xffffffffu, m0, 2));
    m1 = fmaxf(m1, __shfl_xor_sync(0xffffffffu, m1, 1));
    m1 = fmaxf(m1, __shfl_xor_sync(0xffffffffu, m1, 2));

    float s0 = 0.f, s1 = 0.f;
#pragma unroll
    for (int nt = 0; nt < 8; nt++) {
        sacc[nt][0] = __expf(sacc[nt][0] - m0);
        sacc[nt][1] = __expf(sacc[nt][1] - m0);
        sacc[nt][2] = __expf(sacc[nt][2] - m1);
        sacc[nt][3] = __expf(sacc[nt][3] - m1);
        s0 += sacc[nt][0] + sacc[nt][1];
        s1 += sacc[nt][2] + sacc[nt][3];
    }
    s0 += __shfl_xor_sync(0xffffffffu, s0, 1);
    s0 += __shfl_xor_sync(0xffffffffu, s0, 2);
    s1 += __shfl_xor_sync(0xffffffffu, s1, 1);
    s1 += __shfl_xor_sync(0xffffffffu, s1, 2);
    const float i0 = 1.0f / s0, i1 = 1.0f / s1;

    // ---- O = P V ----
    float oacc[4][4];
#pragma unroll
    for (int i = 0; i < 4; i++)
#pragma unroll
        for (int q = 0; q < 4; q++) oacc[i][q] = 0.f;

    const uint32_t vAddr = vB + ((((lane >> 3) & 1) << 3) + (lane & 7)) * 80
                              + (((lane >> 4) & 1) << 4);
#pragma unroll
    for (int kk = 0; kk < 4; kk++) {
        uint32_t pa[4];
        pa[0] = packbf2(sacc[2 * kk][0] * i0,     sacc[2 * kk][1] * i0);
        pa[1] = packbf2(sacc[2 * kk][2] * i1,     sacc[2 * kk][3] * i1);
        pa[2] = packbf2(sacc[2 * kk + 1][0] * i0, sacc[2 * kk + 1][1] * i0);
        pa[3] = packbf2(sacc[2 * kk + 1][2] * i1, sacc[2 * kk + 1][3] * i1);
        uint32_t b0, b1, b2, b3;
        ldsm4t(b0, b1, b2, b3, vAddr + kk * 16 * 80);
        { uint32_t bv0[2] = {b0, b1}, bv1[2] = {b2, b3};
          mma_bf16(oacc[0], pa, bv0); mma_bf16(oacc[1], pa, bv1); }
        ldsm4t(b0, b1, b2, b3, vAddr + kk * 16 * 80 + 32);
        { uint32_t bv0[2] = {b0, b1}, bv1[2] = {b2, b3};
          mma_bf16(oacc[2], pa, bv0); mma_bf16(oacc[3], pa, bv1); }
    }

    bf16* outB = g_attn + (size_t)w * NN * CC + h * HD;
#pragma unroll
    for (int nt = 0; nt < 4; nt++) {
        const int c = nt * 8 + ((lane & 3) << 1);
        if (r0 < NN)
            *(__nv_bfloat162*)&outB[(size_t)r0 * CC + c] =
                __floats2bfloat162_rn(oacc[nt][0], oacc[nt][1]);
        if (r0 + 8 < NN)
            *(__nv_bfloat162*)&outB[(size_t)(r0 + 8) * CC + c] =
                __floats2bfloat162_rn(oacc[nt][2], oacc[nt][3]);
    }
}

// ---------------- launch ----------------
extern "C" void kernel_launch(void* const* d_in, const int* in_sizes, int n_in,
                              void* d_out, int out_size)
{
    const float* x       = (const float*)d_in[0];
    const float* norm1_g = (const float*)d_in[1];
    const float* norm1_b = (const float*)d_in[2];
    const float* qkv_w   = (const float*)d_in[3];
    const float* qkv_b   = (const float*)d_in[4];
    const float* rel_b   = (const float*)d_in[5];
    const float* proj_w  = (const float*)d_in[6];
    const float* proj_b  = (const float*)d_in[7];
    const float* norm2_g = (const float*)d_in[8];
    const float* norm2_b = (const float*)d_in[9];
    const float* fc1_w   = (const float*)d_in[10];
    const float* fc1_b   = (const float*)d_in[11];
    const float* fc2_w   = (const float*)d_in[12];
    const float* fc2_b   = (const float*)d_in[13];
    float* out = (float*)d_out;

    bf16 *p_xw, *p_qkv, *p_attn, *p_xm, *p_h, *p_wqkv, *p_wprj, *p_wfc1, *p_wfc2;
    float *p_y;
    cudaGetSymbolAddress((void**)&p_xw,   g_xw);
    cudaGetSymbolAddress((void**)&p_qkv,  g_qkv);
    cudaGetSymbolAddress((void**)&p_attn, g_attn);
    cudaGetSymbolAddress((void**)&p_y,    g_y);
    cudaGetSymbolAddress((void**)&p_xm,   g_xm);
    cudaGetSymbolAddress((void**)&p_h,    g_h);
    cudaGetSymbolAddress((void**)&p_wqkv, g_wqkv);
    cudaGetSymbolAddress((void**)&p_wprj, g_wprj);
    cudaGetSymbolAddress((void**)&p_wfc1, g_wfc1);
    cudaGetSymbolAddress((void**)&p_wfc2, g_wfc2);

    const int lnBlocks = TOK / 8;

    // 0) merged prep
    prep_kernel<<<456, 256>>>(qkv_w, proj_w, fc1_w, fc2_w, rel_b);

    // 1) LN1 + shift + window partition (bf16)
    ln_kernel<0><<<lnBlocks, 256>>>(x, norm1_g, norm1_b);

    // 2) QKV gemm [TOK,192]x[192,576] -> bf16
    gemm_bf16<0, 0, true><<<dim3(576 / 64, TOK / 128), 128>>>(
        p_xw, p_wqkv, qkv_b, nullptr, p_qkv, TOK, 3 * CC, CC);

    // 3) tensor-core windowed attention (2 heads / block)
    attn_mma_kernel<<<(TOK / NN) * 3, 256>>>();

    // 4) proj gemm + window-reverse/unshift scatter + residual -> g_y (fp32)
    gemm_bf16<0, 2, false><<<dim3(192 / 64, TOK / 128), 128>>>(
        p_attn, p_wprj, proj_b, x, p_y, TOK, CC, CC);

    // 5) LN2 (bf16)
    ln_kernel<1><<<lnBlocks, 256>>>(nullptr, norm2_g, norm2_b);

    // 6) fc1 + exact GELU [TOK,192]x[192,768] -> bf16
    gemm_bf16<1, 0, true><<<dim3(HIDD / 64, TOK / 128), 128>>>(
        p_xm, p_wfc1, fc1_b, nullptr, p_h, TOK, HIDD, CC);

    // 7) fc2 + residual [TOK,768]x[768,192] -> d_out (fp32)
    gemm_bf16<0, 1, false><<<dim3(192 / 64, TOK / 128), 128>>>(
        p_h, p_wfc2, fc2_b, p_y, out, TOK, CC, HIDD);
}

// round 13
// speedup vs baseline: 1.1509x; 1.0760x over previous
#include <cuda_runtime.h>
#include <cuda_bf16.h>
#include <math.h>
#include <stdint.h>

// ---------------- problem constants ----------------
#define BNUM 32
#define HH   56
#define WW   56
#define CC   192
#define NHH  6
#define HD   32
#define WSZ  7
#define SSZ  3
#define NN   49
#define NWIN 64
#define TOK  (BNUM*HH*WW)   // 100352
#define HIDD 768

typedef __nv_bfloat16 bf16;

// ---------------- scratch ----------------
__device__ bf16  g_xw  [(size_t)TOK*CC];
__device__ bf16  g_qkv [(size_t)TOK*3*CC];
__device__ bf16  g_attn[(size_t)TOK*CC];
__device__ float g_y   [(size_t)TOK*CC];
__device__ bf16  g_xm  [(size_t)TOK*CC];
__device__ bf16  g_h   [(size_t)TOK*HIDD];
__device__ float g_tab [4*6*49*64];
__device__ bf16  g_wqkv[(size_t)576*192];
__device__ bf16  g_wprj[(size_t)192*192];
__device__ bf16  g_wfc1[(size_t)HIDD*192];
__device__ bf16  g_wfc2[(size_t)192*HIDD];

// ---------------- PTX helpers ----------------
__device__ __forceinline__ uint32_t smem_u32(const void* p) {
    uint32_t a;
    asm("{ .reg .u64 t; cvta.to.shared.u64 t, %1; cvt.u32.u64 %0, t; }"
        : "=r"(a) : "l"(p));
    return a;
}
__device__ __forceinline__ void cp16(uint32_t s, const void* g) {
    asm volatile("cp.async.cg.shared.global [%0], [%1], 16;" :: "r"(s), "l"(g));
}
#define CP_COMMIT() asm volatile("cp.async.commit_group;" ::: "memory")
__device__ __forceinline__ void ldsm4(uint32_t& r0, uint32_t& r1, uint32_t& r2,
                                      uint32_t& r3, uint32_t a) {
    asm volatile("ldmatrix.sync.aligned.m8n8.x4.shared.b16 {%0,%1,%2,%3}, [%4];"
                 : "=r"(r0), "=r"(r1), "=r"(r2), "=r"(r3) : "r"(a));
}
__device__ __forceinline__ void ldsm4t(uint32_t& r0, uint32_t& r1, uint32_t& r2,
                                       uint32_t& r3, uint32_t a) {
    asm volatile("ldmatrix.sync.aligned.m8n8.x4.trans.shared.b16 {%0,%1,%2,%3}, [%4];"
                 : "=r"(r0), "=r"(r1), "=r"(r2), "=r"(r3) : "r"(a));
}
__device__ __forceinline__ void mma_bf16(float* c, const uint32_t* a, const uint32_t* b) {
    asm volatile(
        "mma.sync.aligned.m16n8k16.row.col.f32.bf16.bf16.f32 "
        "{%0,%1,%2,%3}, {%4,%5,%6,%7}, {%8,%9}, {%0,%1,%2,%3};"
        : "+f"(c[0]), "+f"(c[1]), "+f"(c[2]), "+f"(c[3])
        : "r"(a[0]), "r"(a[1]), "r"(a[2]), "r"(a[3]), "r"(b[0]), "r"(b[1]));
}
__device__ __forceinline__ uint32_t packbf2(float lo, float hi) {
    __nv_bfloat162 h2 = __floats2bfloat162_rn(lo, hi);
    return *reinterpret_cast<uint32_t*>(&h2);
}

// ============ merged prep: 4 weight transposes + bias/mask tables =========
__device__ __forceinline__ void wtrans_tile(const float* W, bf16* Wt,
                                            int K, int N, int bx, int by, int t)
{
    __shared__ float tile[32][33];
    int k0 = by * 32, n0 = bx * 32;
    int tx = t & 31, ty = t >> 5;   // 32 x 8
#pragma unroll
    for (int i = 0; i < 32; i += 8)
        tile[ty + i][tx] = W[(size_t)(k0 + ty + i) * N + n0 + tx];
    __syncthreads();
#pragma unroll
    for (int i = 0; i < 32; i += 8)
        Wt[(size_t)(n0 + ty + i) * K + k0 + tx] = __float2bfloat16(tile[tx][ty + i]);
}

__global__ void prep_kernel(const float* __restrict__ qkv_w,
                            const float* __restrict__ proj_w,
                            const float* __restrict__ fc1_w,
                            const float* __restrict__ fc2_w,
                            const float* __restrict__ rel_bias)
{
    const int b = blockIdx.x;
    const int t = threadIdx.x;
    if (b < 108) {
        wtrans_tile(qkv_w, g_wqkv, CC, 3 * CC, b % 18, b / 18, t);
    } else if (b < 144) {
        int bb = b - 108;
        wtrans_tile(proj_w, g_wprj, CC, CC, bb % 6, bb / 6, t);
    } else if (b < 288) {
        int bb = b - 144;
        wtrans_tile(fc1_w, g_wfc1, CC, HIDD, bb % 24, bb / 24, t);
    } else if (b < 432) {
        int bb = b - 288;
        wtrans_tile(fc2_w, g_wfc2, HIDD, CC, bb % 6, bb / 6, t);
    } else {
        int bh = b - 432;             // 0..23 = mi*6 + h
        int mi = bh / 6, h = bh % 6;
        int eh = mi >> 1, ew = mi & 1;
        for (int idx = t; idx < NN * 64; idx += 256) {
            int i = idx >> 6, j = idx & 63;
            float val;
            if (j >= NN) val = -1e30f;
            else {
                int ih = i / WSZ, iw = i % WSZ, jh = j / WSZ, jw = j % WSZ;
                int dh = ih - jh + (WSZ - 1), dw = iw - jw + (WSZ - 1);
                float bias = rel_bias[(dh * (2 * WSZ - 1) + dw) * NHH + h];
                int ai = eh ? (ih < WSZ - SSZ ? 1 : 2) : 0;
                int bi = ew ? (iw < WSZ - SSZ ? 1 : 2) : 0;
                int aj = eh ? (jh < WSZ - SSZ ? 1 : 2) : 0;
                int bj = ew ? (jw < WSZ - SSZ ? 1 : 2) : 0;
                float mask = ((ai * 3 + bi) != (aj * 3 + bj)) ? -100.0f : 0.0f;
                val = bias + mask;
            }
            g_tab[(size_t)bh * (NN * 64) + idx] = val;
        }
    }
}

// ---------------- LayerNorm (warp per token), bf16 output -----------------
template<int MODE>
__global__ void ln_kernel(const float* __restrict__ x,
                          const float* __restrict__ gamma,
                          const float* __restrict__ beta)
{
    int warp = (blockIdx.x * blockDim.x + threadIdx.x) >> 5;
    int lane = threadIdx.x & 31;
    if (warp >= TOK) return;

    const float* src;
    bf16* dst;
    if (MODE == 0) {
        int tw = warp;
        int w  = tw / NN, n = tw % NN;
        int bb = w / NWIN, wi = w % NWIN;
        int wrow = wi >> 3, wcol = wi & 7;
        int ih = n / WSZ, iw = n % WSZ;
        int gh = wrow * WSZ + ih + SSZ; if (gh >= HH) gh -= HH;
        int gw = wcol * WSZ + iw + SSZ; if (gw >= WW) gw -= WW;
        src = x + ((size_t)bb * HH * WW + (size_t)gh * WW + gw) * CC;
        dst = g_xw + (size_t)tw * CC;
    } else {
        src = g_y + (size_t)warp * CC;
        dst = g_xm + (size_t)warp * CC;
    }

    float v[6];
    float s = 0.f;
#pragma unroll
    for (int k = 0; k < 6; k++) { v[k] = src[lane + 32 * k]; s += v[k]; }
#pragma unroll
    for (int o = 16; o; o >>= 1) s += __shfl_xor_sync(0xffffffffu, s, o);
    float mean = s * (1.0f / CC);
    float vs = 0.f;
#pragma unroll
    for (int k = 0; k < 6; k++) { float d = v[k] - mean; vs += d * d; }
#pragma unroll
    for (int o = 16; o; o >>= 1) vs += __shfl_xor_sync(0xffffffffu, vs, o);
    float inv = rsqrtf(vs * (1.0f / CC) + 1e-5f);
#pragma unroll
    for (int k = 0; k < 6; k++) {
        int c = lane + 32 * k;
        dst[c] = __float2bfloat16((v[k] - mean) * inv * gamma[c] + beta[c]);
    }
}

// ================= bf16 mma GEMM =================
// BM=128, BN=64, BK=64. 128 threads = 4 warps (4m x 1n), warp tile 32x64.
// 2-stage cp.async double buffer, dynamic smem (55.3 KB).
// Row stride 144 B (64 bf16 + 8 pad) -> ldmatrix conflict-free.
// RESM: 0 none, 1 residual (natural), 2 scatter window-reverse + residual.
#define SRB   144                       // smem row bytes
#define A_STG_B (128 * SRB)             // 18432
#define B_STG_B (64  * SRB)             // 9216
#define G_SMEM  (2 * (A_STG_B + B_STG_B))   // 55296

template<int ACT, int RESM, bool OBF>
__global__ void __launch_bounds__(128)
gemm_bf16(const bf16* __restrict__ A, const bf16* __restrict__ Wt,
          const float* __restrict__ bias, const float* __restrict__ res,
          void* __restrict__ Cv, int M, int N, int K)
{
    extern __shared__ __align__(16) char smem[];
    // layout: As0 [0,18432) As1 [18432,36864) Bs0 [36864,46080) Bs1 [46080,55296)
    const uint32_t asB = smem_u32(smem);
    const uint32_t bsB = asB + 2 * A_STG_B;

    const int t    = threadIdx.x;
    const int lane = t & 31;
    const int wid  = t >> 5;          // warp = m-group
    const int m0   = blockIdx.y << 7;
    const int n0   = blockIdx.x << 6;

    const int T = K >> 6;

    auto load_tiles = [&](int kt, int b) {
        const int k0 = kt << 6;
        uint32_t aD = asB + b * A_STG_B;
        // A: 128 rows x 8 chunks (16B) = 1024; 8 per thread
#pragma unroll
        for (int r = 0; r < 8; r++) {
            int i = t + 128 * r;
            int row = i >> 3, c = i & 7;
            cp16(aD + row * SRB + (c << 4),
                 A + (size_t)(m0 + row) * K + k0 + (c << 3));
        }
        // B: 64 rows x 8 chunks = 512; 4 per thread
        uint32_t bD = bsB + b * B_STG_B;
#pragma unroll
        for (int r = 0; r < 4; r++) {
            int i = t + 128 * r;
            int row = i >> 3, c = i & 7;
            cp16(bD + row * SRB + (c << 4),
                 Wt + (size_t)(n0 + row) * K + k0 + (c << 3));
        }
        CP_COMMIT();
    };

    float acc[2][8][4];
#pragma unroll
    for (int i = 0; i < 2; i++)
#pragma unroll
        for (int j = 0; j < 8; j++)
#pragma unroll
            for (int q = 0; q < 4; q++) acc[i][j][q] = 0.f;

    const uint32_t aFrag = (wid * 32 + (lane & 15)) * SRB + ((lane >> 4) << 4);
    const uint32_t bFrag = ((lane & 7) + (((lane >> 4) & 1) << 3)) * SRB
                           + (((lane >> 3) & 1) << 4);

    load_tiles(0, 0);

    for (int kt = 0; kt < T; kt++) {
        const int b = kt & 1;
        if (kt + 1 < T) {
            load_tiles(kt + 1, b ^ 1);
            asm volatile("cp.async.wait_group 1;" ::: "memory");
        } else {
            asm volatile("cp.async.wait_group 0;" ::: "memory");
        }
        __syncthreads();

        const uint32_t aB = asB + b * A_STG_B + aFrag;
        const uint32_t bB = bsB + b * B_STG_B + bFrag;
#pragma unroll
        for (int kk = 0; kk < 4; kk++) {
            uint32_t av[2][4], bv[8][2];
            ldsm4(av[0][0], av[0][1], av[0][2], av[0][3], aB + kk * 32);
            ldsm4(av[1][0], av[1][1], av[1][2], av[1][3], aB + 16 * SRB + kk * 32);
#pragma unroll
            for (int g = 0; g < 4; g++)
                ldsm4(bv[2 * g][0], bv[2 * g][1], bv[2 * g + 1][0], bv[2 * g + 1][1],
                      bB + g * 16 * SRB + kk * 32);
#pragma unroll
            for (int mt = 0; mt < 2; mt++)
#pragma unroll
                for (int nt = 0; nt < 8; nt++)
                    mma_bf16(acc[mt][nt], av[mt], bv[nt]);
        }
        __syncthreads();
    }

    // ---------------- epilogue ----------------
    const int colBase = n0 + ((lane & 3) << 1);
    const int rowBase = m0 + wid * 32 + (lane >> 2);
#pragma unroll
    for (int mt = 0; mt < 2; mt++) {
#pragma unroll
        for (int half = 0; half < 2; half++) {
            const int r = rowBase + mt * 16 + half * 8;
            size_t outRow = (size_t)r;
            if (RESM == 2) {
                int wq = r / NN, nq = r % NN;
                int bq = wq >> 6, wiq = wq & 63;
                int gh = (wiq >> 3) * WSZ + nq / WSZ + SSZ; if (gh >= HH) gh -= HH;
                int gw = (wiq & 7)  * WSZ + nq % WSZ + SSZ; if (gw >= WW) gw -= WW;
                outRow = (size_t)bq * (HH * WW) + gh * WW + gw;
            }
            const float* Rrow = res + outRow * N;
#pragma unroll
            for (int nt = 0; nt < 8; nt++) {
                const int c0 = colBase + nt * 8;
                float v0 = acc[mt][nt][half * 2 + 0] + bias[c0];
                float v1 = acc[mt][nt][half * 2 + 1] + bias[c0 + 1];
                if (ACT == 1) {
                    v0 = 0.5f * v0 * (1.0f + erff(v0 * 0.70710678118654752f));
                    v1 = 0.5f * v1 * (1.0f + erff(v1 * 0.70710678118654752f));
                }
                if (RESM != 0) { v0 += Rrow[c0]; v1 += Rrow[c0 + 1]; }
                if (OBF) {
                    bf16* Crow = (bf16*)Cv + outRow * N;
                    *(__nv_bfloat162*)&Crow[c0] = __floats2bfloat162_rn(v0, v1);
                } else {
                    float* Crow = (float*)Cv + outRow * N;
                    float2 o; o.x = v0; o.y = v1;
                    *(float2*)&Crow[c0] = o;
                }
            }
        }
    }
}

// ================= tensor-core windowed attention: 2 heads / block ========
#define SROW 40
#define ATT_STG (64 * SROW)

__global__ void __launch_bounds__(256)
attn_mma_kernel()
{
    __shared__ __align__(16) bf16 Qs[2][ATT_STG];
    __shared__ __align__(16) bf16 Ks[2][ATT_STG];
    __shared__ __align__(16) bf16 Vs[2][ATT_STG];

    const int blk = blockIdx.x;
    const int w = blk / 3, hp = blk % 3;
    const int t = threadIdx.x;
    const int lane = t & 31;
    const int wid = t >> 5;
    const int hs  = wid >> 2;
    const int mt  = wid & 3;
    const int h   = hp * 2 + hs;

    const uint32_t qB = smem_u32(Qs) + hs * (ATT_STG * 2);
    const uint32_t kB = smem_u32(Ks) + hs * (ATT_STG * 2);
    const uint32_t vB = smem_u32(Vs) + hs * (ATT_STG * 2);

    for (int i = t; i < 2 * 15 * 20; i += 256) {
        int hsel = i / 300, j = i % 300;
        int off = hsel * (ATT_STG / 2) + (49 + j / 20) * 20 + (j % 20);
        ((uint32_t*)Qs)[off] = 0;
        ((uint32_t*)Ks)[off] = 0;
        ((uint32_t*)Vs)[off] = 0;
    }

    const bf16* base = g_qkv + (size_t)w * NN * (3 * CC) + hp * 2 * HD;
    for (int i = t; i < 2 * NN * 4; i += 256) {
        int hsel = i / (NN * 4), j = i % (NN * 4);
        int r = j >> 2, c = (j & 3) << 3;
        const bf16* src = base + (size_t)r * (3 * CC) + hsel * HD + c;
        uint32_t d = hsel * (ATT_STG * 2) + r * 80 + (c << 1);
        cp16(smem_u32(Qs) + d, src);
        cp16(smem_u32(Ks) + d, src + CC);
        cp16(smem_u32(Vs) + d, src + 2 * CC);
    }
    CP_COMMIT();
    asm volatile("cp.async.wait_group 0;" ::: "memory");
    __syncthreads();

    // ---- S = Q K^T ----
    float sacc[8][4];
#pragma unroll
    for (int i = 0; i < 8; i++)
#pragma unroll
        for (int q = 0; q < 4; q++) sacc[i][q] = 0.f;

    const uint32_t aAddr = qB + (mt * 16 + (lane & 15)) * 80 + ((lane >> 4) << 4);
    const uint32_t bAddr = kB + ((lane & 7) + (((lane >> 4) & 1) << 3)) * 80
                              + (((lane >> 3) & 1) << 4);
#pragma unroll
    for (int kk = 0; kk < 2; kk++) {
        uint32_t av[4];
        ldsm4(av[0], av[1], av[2], av[3], aAddr + kk * 32);
#pragma unroll
        for (int ng = 0; ng < 4; ng++) {
            uint32_t b0, b1, b2, b3;
            ldsm4(b0, b1, b2, b3, bAddr + ng * 16 * 80 + kk * 32);
            uint32_t bv0[2] = {b0, b1}, bv1[2] = {b2, b3};
            mma_bf16(sacc[2 * ng],     av, bv0);
            mma_bf16(sacc[2 * ng + 1], av, bv1);
        }
    }

    // ---- scale + table + softmax in fragments ----
    const int wi = w & (NWIN - 1);
    const int mi = (((wi >> 3) == 7) ? 2 : 0) + (((wi & 7) == 7) ? 1 : 0);
    const float* tb = g_tab + (size_t)(mi * NHH + h) * (NN * 64);
    const int r0 = mt * 16 + (lane >> 2);
    const float scale = 0.17677669529663687f;

#pragma unroll
    for (int nt = 0; nt < 8; nt++) {
        const int c = nt * 8 + ((lane & 3) << 1);
        float t00 = 0.f, t01 = 0.f, t10 = 0.f, t11 = 0.f;
        if (r0 < NN)     { float2 tt = *(const float2*)&tb[r0 * 64 + c];      t00 = tt.x; t01 = tt.y; }
        if (r0 + 8 < NN) { float2 tt = *(const float2*)&tb[(r0 + 8) * 64 + c]; t10 = tt.x; t11 = tt.y; }
        sacc[nt][0] = sacc[nt][0] * scale + t00;
        sacc[nt][1] = sacc[nt][1] * scale + t01;
        sacc[nt][2] = sacc[nt][2] * scale + t10;
        sacc[nt][3] = sacc[nt][3] * scale + t11;
    }

    float m0 = -1e30f, m1 = -1e30f;
#pragma unroll
    for (int nt = 0; nt < 8; nt++) {
        m0 = fmaxf(m0, fmaxf(sacc[nt][0], sacc[nt][1]));
        m1 = fmaxf(m1, fmaxf(sacc[nt][2], sacc[nt][3]));
    }
    m0 = fmaxf(m0, __shfl_xor_sync(0xffffffffu, m0, 1));
    m0 = fmaxf(m0, __shfl_xor_sync(0xffffffffu, m0, 2));
    m1 = fmaxf(m1, __shfl_xor_sync(0xffffffffu, m1, 1));
    m1 = fmaxf(m1, __shfl_xor_sync(0xffffffffu, m1, 2));

    float s0 = 0.f, s1 = 0.f;
#pragma unroll
    for (int nt = 0; nt < 8; nt++) {
        sacc[nt][0] = __expf(sacc[nt][0] - m0);
        sacc[nt][1] = __expf(sacc[nt][1] - m0);
        sacc[nt][2] = __expf(sacc[nt][2] - m1);
        sacc[nt][3] = __expf(sacc[nt][3] - m1);
        s0 += sacc[nt][0] + sacc[nt][1];
        s1 += sacc[nt][2] + sacc[nt][3];
    }
    s0 += __shfl_xor_sync(0xffffffffu, s0, 1);
    s0 += __shfl_xor_sync(0xffffffffu, s0, 2);
    s1 += __shfl_xor_sync(0xffffffffu, s1, 1);
    s1 += __shfl_xor_sync(0xffffffffu, s1, 2);
    const float i0 = 1.0f / s0, i1 = 1.0f / s1;

    // ---- O = P V ----
    float oacc[4][4];
#pragma unroll
    for (int i = 0; i < 4; i++)
#pragma unroll
        for (int q = 0; q < 4; q++) oacc[i][q] = 0.f;

    const uint32_t vAddr = vB + ((((lane >> 3) & 1) << 3) + (lane & 7)) * 80
                              + (((lane >> 4) & 1) << 4);
#pragma unroll
    for (int kk = 0; kk < 4; kk++) {
        uint32_t pa[4];
        pa[0] = packbf2(sacc[2 * kk][0] * i0,     sacc[2 * kk][1] * i0);
        pa[1] = packbf2(sacc[2 * kk][2] * i1,     sacc[2 * kk][3] * i1);
        pa[2] = packbf2(sacc[2 * kk + 1][0] * i0, sacc[2 * kk + 1][1] * i0);
        pa[3] = packbf2(sacc[2 * kk + 1][2] * i1, sacc[2 * kk + 1][3] * i1);
        uint32_t b0, b1, b2, b3;
        ldsm4t(b0, b1, b2, b3, vAddr + kk * 16 * 80);
        { uint32_t bv0[2] = {b0, b1}, bv1[2] = {b2, b3};
          mma_bf16(oacc[0], pa, bv0); mma_bf16(oacc[1], pa, bv1); }
        ldsm4t(b0, b1, b2, b3, vAddr + kk * 16 * 80 + 32);
        { uint32_t bv0[2] = {b0, b1}, bv1[2] = {b2, b3};
          mma_bf16(oacc[2], pa, bv0); mma_bf16(oacc[3], pa, bv1); }
    }

    bf16* outB = g_attn + (size_t)w * NN * CC + h * HD;
#pragma unroll
    for (int nt = 0; nt < 4; nt++) {
        const int c = nt * 8 + ((lane & 3) << 1);
        if (r0 < NN)
            *(__nv_bfloat162*)&outB[(size_t)r0 * CC + c] =
                __floats2bfloat162_rn(oacc[nt][0], oacc[nt][1]);
        if (r0 + 8 < NN)
            *(__nv_bfloat162*)&outB[(size_t)(r0 + 8) * CC + c] =
                __floats2bfloat162_rn(oacc[nt][2], oacc[nt][3]);
    }
}

// ---------------- launch ----------------
extern "C" void kernel_launch(void* const* d_in, const int* in_sizes, int n_in,
                              void* d_out, int out_size)
{
    const float* x       = (const float*)d_in[0];
    const float* norm1_g = (const float*)d_in[1];
    const float* norm1_b = (const float*)d_in[2];
    const float* qkv_w   = (const float*)d_in[3];
    const float* qkv_b   = (const float*)d_in[4];
    const float* rel_b   = (const float*)d_in[5];
    const float* proj_w  = (const float*)d_in[6];
    const float* proj_b  = (const float*)d_in[7];
    const float* norm2_g = (const float*)d_in[8];
    const float* norm2_b = (const float*)d_in[9];
    const float* fc1_w   = (const float*)d_in[10];
    const float* fc1_b   = (const float*)d_in[11];
    const float* fc2_w   = (const float*)d_in[12];
    const float* fc2_b   = (const float*)d_in[13];
    float* out = (float*)d_out;

    bf16 *p_xw, *p_qkv, *p_attn, *p_xm, *p_h, *p_wqkv, *p_wprj, *p_wfc1, *p_wfc2;
    float *p_y;
    cudaGetSymbolAddress((void**)&p_xw,   g_xw);
    cudaGetSymbolAddress((void**)&p_qkv,  g_qkv);
    cudaGetSymbolAddress((void**)&p_attn, g_attn);
    cudaGetSymbolAddress((void**)&p_y,    g_y);
    cudaGetSymbolAddress((void**)&p_xm,   g_xm);
    cudaGetSymbolAddress((void**)&p_h,    g_h);
    cudaGetSymbolAddress((void**)&p_wqkv, g_wqkv);
    cudaGetSymbolAddress((void**)&p_wprj, g_wprj);
    cudaGetSymbolAddress((void**)&p_wfc1, g_wfc1);
    cudaGetSymbolAddress((void**)&p_wfc2, g_wfc2);

    cudaFuncSetAttribute(gemm_bf16<0, 0, true>,  cudaFuncAttributeMaxDynamicSharedMemorySize, G_SMEM);
    cudaFuncSetAttribute(gemm_bf16<0, 2, false>, cudaFuncAttributeMaxDynamicSharedMemorySize, G_SMEM);
    cudaFuncSetAttribute(gemm_bf16<1, 0, true>,  cudaFuncAttributeMaxDynamicSharedMemorySize, G_SMEM);
    cudaFuncSetAttribute(gemm_bf16<0, 1, false>, cudaFuncAttributeMaxDynamicSharedMemorySize, G_SMEM);

    const int lnBlocks = TOK / 8;

    // 0) merged prep
    prep_kernel<<<456, 256>>>(qkv_w, proj_w, fc1_w, fc2_w, rel_b);

    // 1) LN1 + shift + window partition (bf16)
    ln_kernel<0><<<lnBlocks, 256>>>(x, norm1_g, norm1_b);

    // 2) QKV gemm [TOK,192]x[192,576] -> bf16
    gemm_bf16<0, 0, true><<<dim3(576 / 64, TOK / 128), 128, G_SMEM>>>(
        p_xw, p_wqkv, qkv_b, nullptr, p_qkv, TOK, 3 * CC, CC);

    // 3) tensor-core windowed attention (2 heads / block)
    attn_mma_kernel<<<(TOK / NN) * 3, 256>>>();

    // 4) proj gemm + window-reverse/unshift scatter + residual -> g_y (fp32)
    gemm_bf16<0, 2, false><<<dim3(192 / 64, TOK / 128), 128, G_SMEM>>>(
        p_attn, p_wprj, proj_b, x, p_y, TOK, CC, CC);

    // 5) LN2 (bf16)
    ln_kernel<1><<<lnBlocks, 256>>>(nullptr, norm2_g, norm2_b);

    // 6) fc1 + exact GELU [TOK,192]x[192,768] -> bf16
    gemm_bf16<1, 0, true><<<dim3(HIDD / 64, TOK / 128), 128, G_SMEM>>>(
        p_xm, p_wfc1, fc1_b, nullptr, p_h, TOK, HIDD, CC);

    // 7) fc2 + residual [TOK,768]x[768,192] -> d_out (fp32)
    gemm_bf16<0, 1, false><<<dim3(192 / 64, TOK / 128), 128, G_SMEM>>>(
        p_h, p_wfc2, fc2_b, p_y, out, TOK, CC, HIDD);
}